// round 13
// baseline (speedup 1.0000x reference)
#include <cuda_runtime.h>
#include <cuda_bf16.h>
#include <math.h>
#include <stdint.h>

#define VSZ  32000
#define EDIM 256
#define DDIM 512
#define BDIM 32
#define TDIM 128
#define SDIM 128
#define PADI 3
#define G4D  2048
#define NCTA 128
#define NTHR 256

// ------------- static device scratch -------------
__device__ float g_X0[(size_t)TDIM * BDIM * G4D];
__device__ float g_A [(size_t)BDIM * TDIM * 2 * DDIM];
__device__ float g_s0[2][BDIM * DDIM];
__device__ float g_s1[2][BDIM * DDIM];
__device__ unsigned g_bar_cnt = 0;
__device__ unsigned g_bar_gen = 0;

__device__ __nv_bfloat16 g_Ah[(size_t)4096 * 1024];
__device__ __nv_bfloat16 g_Al[(size_t)4096 * 1024];
__device__ __nv_bfloat16 g_Bh[(size_t)VSZ * 1024];
__device__ __nv_bfloat16 g_Bl[(size_t)VSZ * 1024];

__device__ __forceinline__ float sigf(float x){ return 1.0f / (1.0f + expf(-x)); }

__device__ __forceinline__ uint32_t smem_u32(const void* p){
    uint32_t a;
    asm("{ .reg .u64 t; cvta.to.shared.u64 t, %1; cvt.u32.u64 %0, t; }" : "=r"(a) : "l"(p));
    return a;
}

// ---- packed f32x2 helpers ----
__device__ __forceinline__ unsigned long long splat2(float x){
    unsigned long long u; unsigned r = __float_as_uint(x);
    asm("mov.b64 %0, {%1, %1};" : "=l"(u) : "r"(r));
    return u;
}
__device__ __forceinline__ void ffma2(unsigned long long& d, unsigned long long a, unsigned long long b){
    asm("fma.rn.f32x2 %0, %1, %2, %3;" : "=l"(d) : "l"(a), "l"(b), "l"(d));
}
__device__ __forceinline__ float2 u2f(unsigned long long u){
    float2 r;
    asm("mov.b64 {%0, %1}, %2;" : "=f"(r.x), "=f"(r.y) : "l"(u));
    return r;
}

#define CP_ASYNC16(dst, src) \
    asm volatile("cp.async.cg.shared.global [%0], [%1], 16;" :: "r"(dst), "l"(src))
#define CP_COMMIT() asm volatile("cp.async.commit_group;" ::: "memory")
#define CP_WAIT(n)  asm volatile("cp.async.wait_group %0;" :: "n"(n) : "memory")

#define LDSM4(r, a) \
    asm volatile("ldmatrix.sync.aligned.m8n8.x4.shared.b16 {%0,%1,%2,%3}, [%4];" \
        : "=r"((r)[0]), "=r"((r)[1]), "=r"((r)[2]), "=r"((r)[3]) : "r"(a))
#define LDSM2(r, a) \
    asm volatile("ldmatrix.sync.aligned.m8n8.x2.shared.b16 {%0,%1}, [%2];" \
        : "=r"((r)[0]), "=r"((r)[1]) : "r"(a))
#define MMA_BF16(d, a, b) \
    asm volatile("mma.sync.aligned.m16n8k16.row.col.f32.bf16.bf16.f32 " \
        "{%0,%1,%2,%3}, {%4,%5,%6,%7}, {%8,%9}, {%0,%1,%2,%3};" \
        : "+f"((d)[0]), "+f"((d)[1]), "+f"((d)[2]), "+f"((d)[3]) \
        : "r"((a)[0]), "r"((a)[1]), "r"((a)[2]), "r"((a)[3]), "r"((b)[0]), "r"((b)[1]))

__device__ __forceinline__ void split2(float x, float y, unsigned& hi, unsigned& lo){
    __nv_bfloat16 hx = __float2bfloat16(x), hy = __float2bfloat16(y);
    __nv_bfloat16 lx = __float2bfloat16(x - __bfloat162float(hx));
    __nv_bfloat16 ly = __float2bfloat16(y - __bfloat162float(hy));
    __nv_bfloat162 hp = __halves2bfloat162(hx, hy), lp = __halves2bfloat162(lx, ly);
    hi = *(unsigned*)&hp; lo = *(unsigned*)&lp;
}

// ------------- init recurrent state -------------
__global__ void k_init(const float* __restrict__ s0, const float* __restrict__ c0){
    int i = blockIdx.x * 256 + threadIdx.x;
    if (i < BDIM * DDIM){
        g_s0[0][i] = s0[i];
        g_s1[0][i] = s0[BDIM * DDIM + i];
    }
}

// ------------- X0 = emb_eff[tok] @ Wih0^T + bih0 + bhh0 -------------
__global__ void k_x0(const int* __restrict__ tar, const float* __restrict__ emb,
                     const float* __restrict__ W, const float* __restrict__ b1,
                     const float* __restrict__ b2){
    __shared__ __align__(16) float Ast[32][68];
    __shared__ __align__(16) float Bst[32][68];
    const int tid = threadIdx.x;
    const int n0 = blockIdx.x * 64, m0 = blockIdx.y * 64;
    const int mg = tid >> 4, ng = tid & 15;
    const int ml0 = mg * 4, nl0 = ng * 4;
    const int kl = tid & 31, rl = tid >> 5;
    unsigned long long acc2[2][4];
    #pragma unroll
    for (int i = 0; i < 2; i++)
        #pragma unroll
        for (int j = 0; j < 4; j++) acc2[i][j] = 0ull;

    for (int kc = 0; kc < EDIM; kc += 32){
        #pragma unroll
        for (int l = 0; l < 8; l++){
            int ml = rl + l * 8;
            int m  = m0 + ml;
            int tt = m >> 5, bb = m & 31;
            int tok = tar[bb * TDIM + tt];
            Ast[kl][ml] = (tok == PADI) ? 0.0f : emb[tok * EDIM + kc + kl];
            int nl = rl + l * 8;
            Bst[kl][nl] = W[(n0 + nl) * EDIM + kc + kl];
        }
        __syncthreads();
        #pragma unroll 8
        for (int k = 0; k < 32; k++){
            ulonglong2 ap = *(const ulonglong2*)&Ast[k][ml0];
            float4 bv = *(const float4*)&Bst[k][nl0];
            unsigned long long bs[4] = { splat2(bv.x), splat2(bv.y), splat2(bv.z), splat2(bv.w) };
            #pragma unroll
            for (int j = 0; j < 4; j++){
                ffma2(acc2[0][j], ap.x, bs[j]);
                ffma2(acc2[1][j], ap.y, bs[j]);
            }
        }
        __syncthreads();
    }
    #pragma unroll
    for (int j = 0; j < 4; j++){
        int n = n0 + nl0 + j;
        float bb2 = b1[n] + b2[n];
        float2 p0 = u2f(acc2[0][j]);
        float2 p1 = u2f(acc2[1][j]);
        g_X0[(size_t)(m0 + ml0 + 0) * G4D + n] = p0.x + bb2;
        g_X0[(size_t)(m0 + ml0 + 1) * G4D + n] = p0.y + bb2;
        g_X0[(size_t)(m0 + ml0 + 2) * G4D + n] = p1.x + bb2;
        g_X0[(size_t)(m0 + ml0 + 3) * G4D + n] = p1.y + bb2;
    }
}

// ------------- persistent recurrence kernel: dual cp.async staging, 1 barrier/step -------------
#define W0STR 129
#define W1STR 257
#define GSTR  33    // gpart row stride (floats)

struct RecSmem {
    float4 W0[16 * W0STR];    // 33.0 KB
    float4 W1[16 * W1STR];    // 65.8 KB
    float4 S4[128 * 32];      // 64 KB   s0 staging
    float4 S1B[128 * 32];     // 64 KB   s1 staging; gpart aliased here
    float  csm0[128];
    float  csm1[128];
    float  bsum[16];
    unsigned gen0;
};

__device__ __forceinline__ void gridbar(unsigned target){
    __syncthreads();
    if (threadIdx.x == 0){
        __threadfence();
        unsigned a = atomicAdd(&g_bar_cnt, 1u);
        if (a == NCTA - 1u){
            g_bar_cnt = 0u;
            __threadfence();
            atomicAdd(&g_bar_gen, 1u);
        } else {
            volatile unsigned* p = &g_bar_gen;
            while ((int)(*p - target) < 0) __nanosleep(32);
        }
        __threadfence();
    }
    __syncthreads();
}

// additive swizzle: row kq (stride 32 f4), col = (b + kq) & 31
__device__ __forceinline__ void stage_async(uint32_t dst_base, const float* __restrict__ Sg, int tid){
    #pragma unroll 4
    for (int i = tid; i < 4096; i += NTHR){
        int b = i >> 7, kq = i & 127;
        uint32_t dst = dst_base + (uint32_t)((kq * 32 + ((b + kq) & 31)) * 16);
        CP_ASYNC16(dst, Sg + b * DDIM + kq * 4);
    }
}

// k-slice GEMM on a stride-32 additive-swizzle buffer
__device__ __forceinline__ void gemm_slice32(
    unsigned long long (&acc2)[4][4],
    const float4* __restrict__ wbase, int wstr,
    const float4* __restrict__ Sbase, int kw, int bg)
{
    #pragma unroll
    for (int kk = 0; kk < 16; kk++){
        const int kq = kw * 16 + kk;
        ulonglong2 wv[4], sv[4];
        #pragma unroll
        for (int i = 0; i < 4; i++)
            wv[i] = *(const ulonglong2*)(wbase + i * 4 * wstr + kk);
        const float4* srow = Sbase + kq * 32;
        #pragma unroll
        for (int j = 0; j < 4; j++)
            sv[j] = *(const ulonglong2*)(srow + ((bg + j * 8 + kq) & 31));
        #pragma unroll
        for (int i = 0; i < 4; i++)
            #pragma unroll
            for (int j = 0; j < 4; j++){
                ffma2(acc2[i][j], wv[i].x, sv[j].x);
                ffma2(acc2[i][j], wv[i].y, sv[j].y);
            }
    }
}

__global__ void __launch_bounds__(NTHR, 1) k_rec(
    const float* __restrict__ c0in,
    const float* __restrict__ Whh0,
    const float* __restrict__ Wih1, const float* __restrict__ Whh1,
    const float* __restrict__ bih1, const float* __restrict__ bhh1)
{
    extern __shared__ RecSmem sm[];
    const int tid = threadIdx.x;
    const int d0  = blockIdx.x * 4;
    const int kw  = tid >> 5;
    const int lane = tid & 31;
    const int rg = lane >> 3;
    const int bg = lane & 7;
    float* gpart = (float*)sm->S1B;           // aliased
    const uint32_t s4_a  = smem_u32(sm->S4);
    const uint32_t s1b_a = smem_u32(sm->S1B);

    if (tid == 0) sm->gen0 = *(volatile unsigned*)&g_bar_gen;
    for (int i = tid; i < 16 * 128; i += NTHR){
        int r_l = i >> 7, kq = i & 127;
        int gr  = (r_l >> 2) * DDIM + d0 + (r_l & 3);
        sm->W0[r_l * W0STR + kq] = *(const float4*)(Whh0 + (size_t)gr * DDIM + kq * 4);
    }
    for (int i = tid; i < 16 * 256; i += NTHR){
        int r_l = i >> 8, kq = i & 255;
        int gr  = (r_l >> 2) * DDIM + d0 + (r_l & 3);
        float4 v;
        if (kq < 128) v = *(const float4*)(Wih1 + (size_t)gr * DDIM + kq * 4);
        else          v = *(const float4*)(Whh1 + (size_t)gr * DDIM + (kq - 128) * 4);
        sm->W1[r_l * W1STR + kq] = v;
    }
    if (tid < 16){
        int gr = (tid >> 2) * DDIM + d0 + (tid & 3);
        sm->bsum[tid] = bih1[gr] + bhh1[gr];
    }
    if (tid < 128){
        int dl = tid >> 5, b = tid & 31;
        sm->csm0[tid] = c0in[b * DDIM + d0 + dl];
        sm->csm1[tid] = c0in[BDIM * DDIM + b * DDIM + d0 + dl];
    }
    __syncthreads();
    const unsigned gen0 = sm->gen0;

    // phase p: cell0(p) [p<T], cell1(p-1) [p>0]. Both inputs ready at phase start.
    for (int p = 0; p <= TDIM; p++){
        const bool do_c0 = (p < TDIM);
        const bool do_c1 = (p > 0);

        // ---- issue both stagings ----
        stage_async(s4_a, g_s0[p & 1], tid);                 // s0[p]
        if (do_c1) stage_async(s1b_a, g_s1[(p + 1) & 1], tid); // s1[p-1]
        CP_COMMIT();

        // X0 prefetch (overlaps cp.async wait)
        float x0v[4] = {0.f, 0.f, 0.f, 0.f};
        if (do_c0 && tid < 128){
            int dl = tid >> 5, b = tid & 31;
            const float* xp = g_X0 + ((size_t)p * BDIM + b) * G4D + d0 + dl;
            #pragma unroll
            for (int q = 0; q < 4; q++) x0v[q] = xp[q * DDIM];
        }
        CP_WAIT(0);
        __syncthreads();

        // ---- all GEMMs back-to-back ----
        unsigned long long acc1[4][4], acc0[4][4];
        #pragma unroll
        for (int i = 0; i < 4; i++)
            #pragma unroll
            for (int j = 0; j < 4; j++){ acc1[i][j] = 0ull; acc0[i][j] = 0ull; }

        if (do_c1){
            gemm_slice32(acc1, sm->W1 + rg * W1STR + kw * 16,       W1STR, sm->S4,  kw, bg);
            gemm_slice32(acc1, sm->W1 + rg * W1STR + 128 + kw * 16, W1STR, sm->S1B, kw, bg);
        }
        if (do_c0)
            gemm_slice32(acc0, sm->W0 + rg * W0STR + kw * 16, W0STR, sm->S4, kw, bg);

        __syncthreads();   // all S1B reads done -> gpart may be written

        if (do_c1){
            #pragma unroll
            for (int i = 0; i < 4; i++)
                #pragma unroll
                for (int j = 0; j < 4; j++){
                    float2 v = u2f(acc1[i][j]);
                    gpart[(kw * 16 + rg + 4 * i) * GSTR + bg + 8 * j] = v.x + v.y;
                }
            __syncthreads();
            if (tid < 128){
                int dl = tid >> 5, b = tid & 31;
                float gv[4];
                #pragma unroll
                for (int q = 0; q < 4; q++){
                    int r_l = q * 4 + dl;
                    float s = 0.f;
                    #pragma unroll
                    for (int w8 = 0; w8 < 8; w8++)
                        s += gpart[(w8 * 16 + r_l) * GSTR + b];
                    gv[q] = s + sm->bsum[r_l];
                }
                float cn = sigf(gv[1]) * sm->csm1[tid] + sigf(gv[0]) * tanhf(gv[2]);
                sm->csm1[tid] = cn;
                float sn = sigf(gv[3]) * tanhf(cn);
                g_s1[p & 1][b * DDIM + d0 + dl] = sn;
                g_A[((size_t)b * TDIM + (p - 1)) * (2 * DDIM) + d0 + dl] = sn;
            }
        }
        __syncthreads();   // pointwise1 gpart reads done -> reuse for cell0

        if (do_c0){
            #pragma unroll
            for (int i = 0; i < 4; i++)
                #pragma unroll
                for (int j = 0; j < 4; j++){
                    float2 v = u2f(acc0[i][j]);
                    gpart[(kw * 16 + rg + 4 * i) * GSTR + bg + 8 * j] = v.x + v.y;
                }
            __syncthreads();
            if (tid < 128){
                int dl = tid >> 5, b = tid & 31;
                float gv[4];
                #pragma unroll
                for (int q = 0; q < 4; q++){
                    int r_l = q * 4 + dl;
                    float s = 0.f;
                    #pragma unroll
                    for (int w8 = 0; w8 < 8; w8++)
                        s += gpart[(w8 * 16 + r_l) * GSTR + b];
                    gv[q] = s + x0v[q];
                }
                float cn = sigf(gv[1]) * sm->csm0[tid] + sigf(gv[0]) * tanhf(gv[2]);
                sm->csm0[tid] = cn;
                g_s0[(p + 1) & 1][b * DDIM + d0 + dl] = sigf(gv[3]) * tanhf(cn);
            }
        }

        gridbar(gen0 + p + 1);
    }
}

// ------------- parallel attention + direct bf16-split write -------------
__global__ void __launch_bounds__(256) k_attn2(const float* __restrict__ h){
    __shared__ __align__(16) float s1s[8][516];
    __shared__ float sc[8][132];
    const int b = blockIdx.y, t0 = blockIdx.x * 8;
    const int tid = threadIdx.x, w = tid >> 5, lane = tid & 31;
    const size_t arow0 = ((size_t)b * TDIM + t0) * 1024;

    for (int i = tid; i < 1024; i += 256){
        int tt = i >> 7, q = i & 127;
        *(float4*)&s1s[tt][q * 4] = *(const float4*)(g_A + arow0 + (size_t)tt * 1024 + q * 4);
    }
    __syncthreads();

    const float* hb = h + (size_t)b * SDIM * DDIM;

    for (int j = 0; j < 16; j++){
        int s = w * 16 + j;
        const float4* hr = (const float4*)(hb + (size_t)s * DDIM);
        float4 hv[4];
        #pragma unroll
        for (int q = 0; q < 4; q++) hv[q] = hr[lane + 32 * q];
        float p[8];
        #pragma unroll
        for (int tt = 0; tt < 8; tt++){
            float acc = 0.f;
            #pragma unroll
            for (int q = 0; q < 4; q++){
                float4 sv = *(const float4*)&s1s[tt][(lane + 32 * q) * 4];
                acc += hv[q].x * sv.x + hv[q].y * sv.y + hv[q].z * sv.z + hv[q].w * sv.w;
            }
            p[tt] = acc;
        }
        #pragma unroll
        for (int tt = 0; tt < 8; tt++){
            #pragma unroll
            for (int off = 16; off; off >>= 1)
                p[tt] += __shfl_xor_sync(0xffffffffu, p[tt], off);
        }
        #pragma unroll
        for (int tt = 0; tt < 8; tt++)
            if (lane == tt) sc[tt][s] = p[tt];
    }
    __syncthreads();

    {
        float x[4];
        #pragma unroll
        for (int q = 0; q < 4; q++) x[q] = sc[w][lane + 32 * q];
        float mx = fmaxf(fmaxf(x[0], x[1]), fmaxf(x[2], x[3]));
        #pragma unroll
        for (int off = 16; off; off >>= 1) mx = fmaxf(mx, __shfl_xor_sync(0xffffffffu, mx, off));
        float e[4], sum = 0.f;
        #pragma unroll
        for (int q = 0; q < 4; q++){ e[q] = expf(x[q] - mx); sum += e[q]; }
        #pragma unroll
        for (int off = 16; off; off >>= 1) sum += __shfl_xor_sync(0xffffffffu, sum, off);
        float inv = 1.0f / sum;
        #pragma unroll
        for (int q = 0; q < 4; q++) sc[w][lane + 32 * q] = e[q] * inv;
    }
    __syncthreads();

    float az[8][2] = {};
    const int d2 = tid * 2;
    #pragma unroll 4
    for (int s = 0; s < SDIM; s++){
        float2 hv = *(const float2*)(hb + (size_t)s * DDIM + d2);
        #pragma unroll
        for (int tt = 0; tt < 8; tt++){
            float a = sc[tt][s];
            az[tt][0] += a * hv.x;
            az[tt][1] += a * hv.y;
        }
    }
    #pragma unroll
    for (int tt = 0; tt < 8; tt++){
        unsigned hi, lo;
        split2(az[tt][0], az[tt][1], hi, lo);
        size_t off = arow0 + (size_t)tt * 1024 + 512 + d2;
        *(unsigned*)(g_Ah + off) = hi;
        *(unsigned*)(g_Al + off) = lo;
    }
    for (int i = tid; i < 2048; i += 256){
        int tt = i >> 8, q = i & 255;
        float x = s1s[tt][q * 2], y = s1s[tt][q * 2 + 1];
        unsigned hi, lo;
        split2(x, y, hi, lo);
        size_t off = arow0 + (size_t)tt * 1024 + q * 2;
        *(unsigned*)(g_Ah + off) = hi;
        *(unsigned*)(g_Al + off) = lo;
    }
}

// ------------- bf16 hi/lo split of Wout -------------
__global__ void k_cvtW(const float* __restrict__ W){
    const size_t total = (size_t)VSZ * 1024 / 4;
    for (size_t i = (size_t)blockIdx.x * blockDim.x + threadIdx.x; i < total;
         i += (size_t)gridDim.x * blockDim.x){
        float4 v = ((const float4*)W)[i];
        unsigned h0, l0, h1, l1;
        split2(v.x, v.y, h0, l0);
        split2(v.z, v.w, h1, l1);
        ((uint2*)g_Bh)[i] = make_uint2(h0, h1);
        ((uint2*)g_Bl)[i] = make_uint2(l0, l1);
    }
}

// ------------- output GEMM via mma.sync bf16 (3-term split) -------------
#define OST 65536
#define OAH 0
#define OAL 16384
#define OBH 32768
#define OBL 49152

__device__ __forceinline__ uint32_t osw(uint32_t r, uint32_t c8){
    return r * 128u + ((c8 ^ (r & 7u)) * 16u);
}

__global__ void __launch_bounds__(256, 1) k_out_mma(float* __restrict__ out,
                                                    const float* __restrict__ bout){
    extern __shared__ char osm[];
    __shared__ float bias[128];
    const uint32_t sb = smem_u32(osm);
    const int tid = threadIdx.x;
    const int wid = tid >> 5, lane = tid & 31;
    const int wm = wid >> 2, wn = wid & 3;
    const int m0 = blockIdx.x * 128;
    const int n0 = blockIdx.y * 128;

    if (tid < 128) bias[tid] = bout[n0 + tid];

    auto load_chunk = [&](int st, int kc){
        const uint32_t stb = sb + (uint32_t)st * OST;
        #pragma unroll
        for (int q = 0; q < 8; q++){
            int i = tid + q * 256;
            int r = (i & 1023) >> 3, c8 = i & 7;
            const __nv_bfloat16* src = (i < 1024) ? g_Ah : g_Al;
            uint32_t dst = stb + (i < 1024 ? OAH : OAL) + osw((uint32_t)r, (uint32_t)c8);
            CP_ASYNC16(dst, src + (size_t)(m0 + r) * 1024 + kc + c8 * 8);
        }
        #pragma unroll
        for (int q = 0; q < 8; q++){
            int i = tid + q * 256;
            int r = (i & 1023) >> 3, c8 = i & 7;
            const __nv_bfloat16* src = (i < 1024) ? g_Bh : g_Bl;
            uint32_t dst = stb + (i < 1024 ? OBH : OBL) + osw((uint32_t)r, (uint32_t)c8);
            CP_ASYNC16(dst, src + (size_t)(n0 + r) * 1024 + kc + c8 * 8);
        }
        CP_COMMIT();
    };

    float acc[4][4][4] = {};

    load_chunk(0, 0);
    load_chunk(1, 64);
    load_chunk(2, 128);

    #pragma unroll 1
    for (int c = 0; c < 16; c++){
        if      (c < 14) { CP_WAIT(2); }
        else if (c == 14){ CP_WAIT(1); }
        else             { CP_WAIT(0); }
        __syncthreads();

        const uint32_t base = sb + (uint32_t)(c % 3) * OST;
        #pragma unroll
        for (int ks = 0; ks < 4; ks++){
            const int k0 = ks * 16;
            uint32_t Ah[4][4], Al[4][4], Bh[4][2], Bl[4][2];
            {
                uint32_t arow = (uint32_t)(wm * 64 + ((lane >> 3) & 1) * 8 + (lane & 7));
                uint32_t ac8  = (uint32_t)((k0 >> 3) + (lane >> 4));
                #pragma unroll
                for (int f = 0; f < 4; f++){
                    uint32_t off = osw(arow + f * 16, ac8);
                    LDSM4(Ah[f], base + OAH + off);
                    LDSM4(Al[f], base + OAL + off);
                }
            }
            {
                uint32_t brow = (uint32_t)(wn * 32 + (lane & 7));
                uint32_t bc8  = (uint32_t)((k0 >> 3) + ((lane >> 3) & 1));
                #pragma unroll
                for (int g = 0; g < 4; g++){
                    uint32_t off = osw(brow + g * 8, bc8);
                    LDSM2(Bh[g], base + OBH + off);
                    LDSM2(Bl[g], base + OBL + off);
                }
            }
            #pragma unroll
            for (int f = 0; f < 4; f++)
                #pragma unroll
                for (int g = 0; g < 4; g++){
                    MMA_BF16(acc[f][g], Ah[f], Bh[g]);
                    MMA_BF16(acc[f][g], Al[f], Bh[g]);
                    MMA_BF16(acc[f][g], Ah[f], Bl[g]);
                }
        }
        __syncthreads();
        if (c + 3 < 16) load_chunk((c + 3) % 3, (c + 3) * 64);
    }

    const size_t ob = (size_t)blockIdx.x * VSZ * TDIM;
    #pragma unroll
    for (int f = 0; f < 4; f++){
        int m = wm * 64 + f * 16 + (lane >> 2);
        #pragma unroll
        for (int g = 0; g < 4; g++){
            int n = wn * 32 + g * 8 + (lane & 3) * 2;
            float* p = out + ob + (size_t)(n0 + n) * TDIM + m;
            p[0]        = acc[f][g][0] + bias[n];
            p[TDIM]     = acc[f][g][1] + bias[n + 1];
            p[8]        = acc[f][g][2] + bias[n];
            p[8 + TDIM] = acc[f][g][3] + bias[n + 1];
        }
    }
}

// ------------- launcher -------------
extern "C" void kernel_launch(void* const* d_in, const int* in_sizes, int n_in,
                              void* d_out, int out_size){
    const int*   tar  = (const int*)  d_in[0];
    const float* h    = (const float*)d_in[1];
    const float* s0   = (const float*)d_in[2];
    const float* c0   = (const float*)d_in[3];
    const float* emb  = (const float*)d_in[4];
    const float* Wih0 = (const float*)d_in[5];
    const float* Whh0 = (const float*)d_in[6];
    const float* bih0 = (const float*)d_in[7];
    const float* bhh0 = (const float*)d_in[8];
    const float* Wih1 = (const float*)d_in[9];
    const float* Whh1 = (const float*)d_in[10];
    const float* bih1 = (const float*)d_in[11];
    const float* bhh1 = (const float*)d_in[12];
    const float* Wout = (const float*)d_in[13];
    const float* bout = (const float*)d_in[14];
    float* out = (float*)d_out;

    static int attr_set = 0;
    static cudaStream_t s2 = nullptr;
    static cudaEvent_t ev1 = nullptr, ev2 = nullptr;
    if (!attr_set){
        cudaFuncSetAttribute(k_rec, cudaFuncAttributeMaxDynamicSharedMemorySize,
                             (int)sizeof(RecSmem));
        cudaFuncSetAttribute(k_out_mma, cudaFuncAttributeMaxDynamicSharedMemorySize,
                             3 * OST);
        cudaStreamCreateWithFlags(&s2, cudaStreamNonBlocking);
        cudaEventCreateWithFlags(&ev1, cudaEventDisableTiming);
        cudaEventCreateWithFlags(&ev2, cudaEventDisableTiming);
        attr_set = 1;
    }

    // fork: cvtW (independent until k_out_mma) runs on s2 in parallel
    cudaEventRecord(ev1, 0);
    cudaStreamWaitEvent(s2, ev1, 0);
    k_cvtW<<<2048, 256, 0, s2>>>(Wout);
    cudaEventRecord(ev2, s2);

    k_init<<<64, 256>>>(s0, c0);
    k_x0<<<dim3(32, 64), 256>>>(tar, emb, Wih0, bih0, bhh0);
    k_rec<<<NCTA, NTHR, sizeof(RecSmem)>>>(c0, Whh0, Wih1, Whh1, bih1, bhh1);
    k_attn2<<<dim3(16, 32), 256>>>(h);

    cudaStreamWaitEvent(0, ev2, 0);
    k_out_mma<<<dim3(32, 250), 256, 3 * OST>>>(out, bout);
}

// round 14
// speedup vs baseline: 1.1249x; 1.1249x over previous
#include <cuda_runtime.h>
#include <cuda_bf16.h>
#include <math.h>
#include <stdint.h>

#define VSZ  32000
#define EDIM 256
#define DDIM 512
#define BDIM 32
#define TDIM 128
#define SDIM 128
#define PADI 3
#define G4D  2048
#define NCTA 128
#define NTHR 256

// ------------- static device scratch -------------
__device__ float g_X0[(size_t)TDIM * BDIM * G4D];
__device__ float g_A [(size_t)BDIM * TDIM * 2 * DDIM];
__device__ float g_s0[2][BDIM * DDIM];
__device__ float g_s1[2][BDIM * DDIM];
__device__ unsigned g_bar_cnt = 0;
__device__ unsigned g_bar_gen = 0;

__device__ __nv_bfloat16 g_Ah[(size_t)4096 * 1024];
__device__ __nv_bfloat16 g_Al[(size_t)4096 * 1024];
__device__ __nv_bfloat16 g_Bh[(size_t)VSZ * 1024];
__device__ __nv_bfloat16 g_Bl[(size_t)VSZ * 1024];

__device__ __forceinline__ float sigf(float x){ return 1.0f / (1.0f + expf(-x)); }

__device__ __forceinline__ uint32_t smem_u32(const void* p){
    uint32_t a;
    asm("{ .reg .u64 t; cvta.to.shared.u64 t, %1; cvt.u32.u64 %0, t; }" : "=r"(a) : "l"(p));
    return a;
}

// ---- packed f32x2 helpers ----
__device__ __forceinline__ unsigned long long splat2(float x){
    unsigned long long u; unsigned r = __float_as_uint(x);
    asm("mov.b64 %0, {%1, %1};" : "=l"(u) : "r"(r));
    return u;
}
__device__ __forceinline__ void ffma2(unsigned long long& d, unsigned long long a, unsigned long long b){
    asm("fma.rn.f32x2 %0, %1, %2, %3;" : "=l"(d) : "l"(a), "l"(b), "l"(d));
}
__device__ __forceinline__ float2 u2f(unsigned long long u){
    float2 r;
    asm("mov.b64 {%0, %1}, %2;" : "=f"(r.x), "=f"(r.y) : "l"(u));
    return r;
}

#define CP_ASYNC16(dst, src) \
    asm volatile("cp.async.cg.shared.global [%0], [%1], 16;" :: "r"(dst), "l"(src))
#define CP_COMMIT() asm volatile("cp.async.commit_group;" ::: "memory")
#define CP_WAIT(n)  asm volatile("cp.async.wait_group %0;" :: "n"(n) : "memory")

#define LDSM4(r, a) \
    asm volatile("ldmatrix.sync.aligned.m8n8.x4.shared.b16 {%0,%1,%2,%3}, [%4];" \
        : "=r"((r)[0]), "=r"((r)[1]), "=r"((r)[2]), "=r"((r)[3]) : "r"(a))
#define LDSM2(r, a) \
    asm volatile("ldmatrix.sync.aligned.m8n8.x2.shared.b16 {%0,%1}, [%2];" \
        : "=r"((r)[0]), "=r"((r)[1]) : "r"(a))
#define MMA_BF16(d, a, b) \
    asm volatile("mma.sync.aligned.m16n8k16.row.col.f32.bf16.bf16.f32 " \
        "{%0,%1,%2,%3}, {%4,%5,%6,%7}, {%8,%9}, {%0,%1,%2,%3};" \
        : "+f"((d)[0]), "+f"((d)[1]), "+f"((d)[2]), "+f"((d)[3]) \
        : "r"((a)[0]), "r"((a)[1]), "r"((a)[2]), "r"((a)[3]), "r"((b)[0]), "r"((b)[1]))

__device__ __forceinline__ void split2(float x, float y, unsigned& hi, unsigned& lo){
    __nv_bfloat16 hx = __float2bfloat16(x), hy = __float2bfloat16(y);
    __nv_bfloat16 lx = __float2bfloat16(x - __bfloat162float(hx));
    __nv_bfloat16 ly = __float2bfloat16(y - __bfloat162float(hy));
    __nv_bfloat162 hp = __halves2bfloat162(hx, hy), lp = __halves2bfloat162(lx, ly);
    hi = *(unsigned*)&hp; lo = *(unsigned*)&lp;
}

// ------------- init recurrent state -------------
__global__ void k_init(const float* __restrict__ s0, const float* __restrict__ c0){
    int i = blockIdx.x * 256 + threadIdx.x;
    if (i < BDIM * DDIM){
        g_s0[0][i] = s0[i];
        g_s1[0][i] = s0[BDIM * DDIM + i];
    }
}

// ------------- X0 = emb_eff[tok] @ Wih0^T + bih0 + bhh0 -------------
__global__ void k_x0(const int* __restrict__ tar, const float* __restrict__ emb,
                     const float* __restrict__ W, const float* __restrict__ b1,
                     const float* __restrict__ b2){
    __shared__ __align__(16) float Ast[32][68];
    __shared__ __align__(16) float Bst[32][68];
    const int tid = threadIdx.x;
    const int n0 = blockIdx.x * 64, m0 = blockIdx.y * 64;
    const int mg = tid >> 4, ng = tid & 15;
    const int ml0 = mg * 4, nl0 = ng * 4;
    const int kl = tid & 31, rl = tid >> 5;
    unsigned long long acc2[2][4];
    #pragma unroll
    for (int i = 0; i < 2; i++)
        #pragma unroll
        for (int j = 0; j < 4; j++) acc2[i][j] = 0ull;

    for (int kc = 0; kc < EDIM; kc += 32){
        #pragma unroll
        for (int l = 0; l < 8; l++){
            int ml = rl + l * 8;
            int m  = m0 + ml;
            int tt = m >> 5, bb = m & 31;
            int tok = tar[bb * TDIM + tt];
            Ast[kl][ml] = (tok == PADI) ? 0.0f : emb[tok * EDIM + kc + kl];
            int nl = rl + l * 8;
            Bst[kl][nl] = W[(n0 + nl) * EDIM + kc + kl];
        }
        __syncthreads();
        #pragma unroll 8
        for (int k = 0; k < 32; k++){
            ulonglong2 ap = *(const ulonglong2*)&Ast[k][ml0];
            float4 bv = *(const float4*)&Bst[k][nl0];
            unsigned long long bs[4] = { splat2(bv.x), splat2(bv.y), splat2(bv.z), splat2(bv.w) };
            #pragma unroll
            for (int j = 0; j < 4; j++){
                ffma2(acc2[0][j], ap.x, bs[j]);
                ffma2(acc2[1][j], ap.y, bs[j]);
            }
        }
        __syncthreads();
    }
    #pragma unroll
    for (int j = 0; j < 4; j++){
        int n = n0 + nl0 + j;
        float bb2 = b1[n] + b2[n];
        float2 p0 = u2f(acc2[0][j]);
        float2 p1 = u2f(acc2[1][j]);
        g_X0[(size_t)(m0 + ml0 + 0) * G4D + n] = p0.x + bb2;
        g_X0[(size_t)(m0 + ml0 + 1) * G4D + n] = p0.y + bb2;
        g_X0[(size_t)(m0 + ml0 + 2) * G4D + n] = p1.x + bb2;
        g_X0[(size_t)(m0 + ml0 + 3) * G4D + n] = p1.y + bb2;
    }
}

// ------------- persistent recurrence: dual cp.async staging, serialized cells -------------
#define W0STR 129
#define W1STR 257
#define GSTR  33

struct RecSmem {
    float4 W0[16 * W0STR];    // 33.0 KB
    float4 W1[16 * W1STR];    // 65.8 KB
    float4 S4[128 * 32];      // 64 KB   s0 staging
    float4 S1B[128 * 32];     // 64 KB   s1 staging; gpart aliased here
    float  csm0[128];
    float  csm1[128];
    float  bsum[16];
    unsigned gen0;
};

__device__ __forceinline__ void gridbar(unsigned target){
    __syncthreads();
    if (threadIdx.x == 0){
        __threadfence();
        unsigned a = atomicAdd(&g_bar_cnt, 1u);
        if (a == NCTA - 1u){
            g_bar_cnt = 0u;
            __threadfence();
            atomicAdd(&g_bar_gen, 1u);
        } else {
            volatile unsigned* p = &g_bar_gen;
            while ((int)(*p - target) < 0) __nanosleep(32);
        }
        __threadfence();
    }
    __syncthreads();
}

// additive swizzle: row kq (stride 32 f4), col = (b + kq) & 31
__device__ __forceinline__ void stage_async(uint32_t dst_base, const float* __restrict__ Sg, int tid){
    #pragma unroll 4
    for (int i = tid; i < 4096; i += NTHR){
        int b = i >> 7, kq = i & 127;
        uint32_t dst = dst_base + (uint32_t)((kq * 32 + ((b + kq) & 31)) * 16);
        CP_ASYNC16(dst, Sg + b * DDIM + kq * 4);
    }
}

// k-slice GEMM on a stride-32 additive-swizzle buffer
__device__ __forceinline__ void gemm_slice32(
    unsigned long long (&acc2)[4][4],
    const float4* __restrict__ wbase, int wstr,
    const float4* __restrict__ Sbase, int kw, int bg)
{
    #pragma unroll
    for (int kk = 0; kk < 16; kk++){
        const int kq = kw * 16 + kk;
        ulonglong2 wv[4], sv[4];
        #pragma unroll
        for (int i = 0; i < 4; i++)
            wv[i] = *(const ulonglong2*)(wbase + i * 4 * wstr + kk);
        const float4* srow = Sbase + kq * 32;
        #pragma unroll
        for (int j = 0; j < 4; j++)
            sv[j] = *(const ulonglong2*)(srow + ((bg + j * 8 + kq) & 31));
        #pragma unroll
        for (int i = 0; i < 4; i++)
            #pragma unroll
            for (int j = 0; j < 4; j++){
                ffma2(acc2[i][j], wv[i].x, sv[j].x);
                ffma2(acc2[i][j], wv[i].y, sv[j].y);
            }
    }
}

__global__ void __launch_bounds__(NTHR, 1) k_rec(
    const float* __restrict__ c0in,
    const float* __restrict__ Whh0,
    const float* __restrict__ Wih1, const float* __restrict__ Whh1,
    const float* __restrict__ bih1, const float* __restrict__ bhh1)
{
    extern __shared__ RecSmem sm[];
    const int tid = threadIdx.x;
    const int d0  = blockIdx.x * 4;
    const int kw  = tid >> 5;
    const int lane = tid & 31;
    const int rg = lane >> 3;
    const int bg = lane & 7;
    float* gpart = (float*)sm->S1B;
    const uint32_t s4_a  = smem_u32(sm->S4);
    const uint32_t s1b_a = smem_u32(sm->S1B);

    if (tid == 0) sm->gen0 = *(volatile unsigned*)&g_bar_gen;
    for (int i = tid; i < 16 * 128; i += NTHR){
        int r_l = i >> 7, kq = i & 127;
        int gr  = (r_l >> 2) * DDIM + d0 + (r_l & 3);
        sm->W0[r_l * W0STR + kq] = *(const float4*)(Whh0 + (size_t)gr * DDIM + kq * 4);
    }
    for (int i = tid; i < 16 * 256; i += NTHR){
        int r_l = i >> 8, kq = i & 255;
        int gr  = (r_l >> 2) * DDIM + d0 + (r_l & 3);
        float4 v;
        if (kq < 128) v = *(const float4*)(Wih1 + (size_t)gr * DDIM + kq * 4);
        else          v = *(const float4*)(Whh1 + (size_t)gr * DDIM + (kq - 128) * 4);
        sm->W1[r_l * W1STR + kq] = v;
    }
    if (tid < 16){
        int gr = (tid >> 2) * DDIM + d0 + (tid & 3);
        sm->bsum[tid] = bih1[gr] + bhh1[gr];
    }
    if (tid < 128){
        int dl = tid >> 5, b = tid & 31;
        sm->csm0[tid] = c0in[b * DDIM + d0 + dl];
        sm->csm1[tid] = c0in[BDIM * DDIM + b * DDIM + d0 + dl];
    }
    __syncthreads();
    const unsigned gen0 = sm->gen0;

    // phase p: cell1(p-1) then cell0(p). Both inputs staged up-front.
    for (int p = 0; p <= TDIM; p++){
        const bool do_c0 = (p < TDIM);
        const bool do_c1 = (p > 0);

        // ---- issue both stagings ----
        stage_async(s4_a, g_s0[p & 1], tid);                    // s0[p]
        if (do_c1) stage_async(s1b_a, g_s1[(p + 1) & 1], tid);  // s1[p-1]
        CP_COMMIT();

        // X0 prefetch (overlaps cp.async)
        float x0v[4] = {0.f, 0.f, 0.f, 0.f};
        if (do_c0 && tid < 128){
            int dl = tid >> 5, b = tid & 31;
            const float* xp = g_X0 + ((size_t)p * BDIM + b) * G4D + d0 + dl;
            #pragma unroll
            for (int q = 0; q < 4; q++) x0v[q] = xp[q * DDIM];
        }
        CP_WAIT(0);
        __syncthreads();

        // ================= cell1(p-1): full K, single accumulator =================
        if (do_c1){
            unsigned long long acc1[4][4];
            #pragma unroll
            for (int i = 0; i < 4; i++)
                #pragma unroll
                for (int j = 0; j < 4; j++) acc1[i][j] = 0ull;

            gemm_slice32(acc1, sm->W1 + rg * W1STR + kw * 16,       W1STR, sm->S4,  kw, bg);
            gemm_slice32(acc1, sm->W1 + rg * W1STR + 128 + kw * 16, W1STR, sm->S1B, kw, bg);
            __syncthreads();   // all S1B reads done -> gpart writable
            #pragma unroll
            for (int i = 0; i < 4; i++)
                #pragma unroll
                for (int j = 0; j < 4; j++){
                    float2 v = u2f(acc1[i][j]);
                    gpart[(kw * 16 + rg + 4 * i) * GSTR + bg + 8 * j] = v.x + v.y;
                }
            __syncthreads();
            if (tid < 128){
                int dl = tid >> 5, b = tid & 31;
                float gv[4];
                #pragma unroll
                for (int q = 0; q < 4; q++){
                    int r_l = q * 4 + dl;
                    float s = 0.f;
                    #pragma unroll
                    for (int w8 = 0; w8 < 8; w8++)
                        s += gpart[(w8 * 16 + r_l) * GSTR + b];
                    gv[q] = s + sm->bsum[r_l];
                }
                float cn = sigf(gv[1]) * sm->csm1[tid] + sigf(gv[0]) * tanhf(gv[2]);
                sm->csm1[tid] = cn;
                float sn = sigf(gv[3]) * tanhf(cn);
                g_s1[p & 1][b * DDIM + d0 + dl] = sn;
                g_A[((size_t)b * TDIM + (p - 1)) * (2 * DDIM) + d0 + dl] = sn;
            }
            __syncthreads();   // pointwise1 gpart reads done
        }

        // ================= cell0(p) =================
        if (do_c0){
            unsigned long long acc0[4][4];
            #pragma unroll
            for (int i = 0; i < 4; i++)
                #pragma unroll
                for (int j = 0; j < 4; j++) acc0[i][j] = 0ull;

            gemm_slice32(acc0, sm->W0 + rg * W0STR + kw * 16, W0STR, sm->S4, kw, bg);
            if (!do_c1) __syncthreads();   // p==0: ensure gpart region safe (no-op ordering)
            #pragma unroll
            for (int i = 0; i < 4; i++)
                #pragma unroll
                for (int j = 0; j < 4; j++){
                    float2 v = u2f(acc0[i][j]);
                    gpart[(kw * 16 + rg + 4 * i) * GSTR + bg + 8 * j] = v.x + v.y;
                }
            __syncthreads();
            if (tid < 128){
                int dl = tid >> 5, b = tid & 31;
                float gv[4];
                #pragma unroll
                for (int q = 0; q < 4; q++){
                    int r_l = q * 4 + dl;
                    float s = 0.f;
                    #pragma unroll
                    for (int w8 = 0; w8 < 8; w8++)
                        s += gpart[(w8 * 16 + r_l) * GSTR + b];
                    gv[q] = s + x0v[q];
                }
                float cn = sigf(gv[1]) * sm->csm0[tid] + sigf(gv[0]) * tanhf(gv[2]);
                sm->csm0[tid] = cn;
                g_s0[(p + 1) & 1][b * DDIM + d0 + dl] = sigf(gv[3]) * tanhf(cn);
            }
        }

        gridbar(gen0 + p + 1);
    }
}

// ------------- parallel attention + direct bf16-split write -------------
__global__ void __launch_bounds__(256) k_attn2(const float* __restrict__ h){
    __shared__ __align__(16) float s1s[8][516];
    __shared__ float sc[8][132];
    const int b = blockIdx.y, t0 = blockIdx.x * 8;
    const int tid = threadIdx.x, w = tid >> 5, lane = tid & 31;
    const size_t arow0 = ((size_t)b * TDIM + t0) * 1024;

    for (int i = tid; i < 1024; i += 256){
        int tt = i >> 7, q = i & 127;
        *(float4*)&s1s[tt][q * 4] = *(const float4*)(g_A + arow0 + (size_t)tt * 1024 + q * 4);
    }
    __syncthreads();

    const float* hb = h + (size_t)b * SDIM * DDIM;

    for (int j = 0; j < 16; j++){
        int s = w * 16 + j;
        const float4* hr = (const float4*)(hb + (size_t)s * DDIM);
        float4 hv[4];
        #pragma unroll
        for (int q = 0; q < 4; q++) hv[q] = hr[lane + 32 * q];
        float p[8];
        #pragma unroll
        for (int tt = 0; tt < 8; tt++){
            float acc = 0.f;
            #pragma unroll
            for (int q = 0; q < 4; q++){
                float4 sv = *(const float4*)&s1s[tt][(lane + 32 * q) * 4];
                acc += hv[q].x * sv.x + hv[q].y * sv.y + hv[q].z * sv.z + hv[q].w * sv.w;
            }
            p[tt] = acc;
        }
        #pragma unroll
        for (int tt = 0; tt < 8; tt++){
            #pragma unroll
            for (int off = 16; off; off >>= 1)
                p[tt] += __shfl_xor_sync(0xffffffffu, p[tt], off);
        }
        #pragma unroll
        for (int tt = 0; tt < 8; tt++)
            if (lane == tt) sc[tt][s] = p[tt];
    }
    __syncthreads();

    {
        float x[4];
        #pragma unroll
        for (int q = 0; q < 4; q++) x[q] = sc[w][lane + 32 * q];
        float mx = fmaxf(fmaxf(x[0], x[1]), fmaxf(x[2], x[3]));
        #pragma unroll
        for (int off = 16; off; off >>= 1) mx = fmaxf(mx, __shfl_xor_sync(0xffffffffu, mx, off));
        float e[4], sum = 0.f;
        #pragma unroll
        for (int q = 0; q < 4; q++){ e[q] = expf(x[q] - mx); sum += e[q]; }
        #pragma unroll
        for (int off = 16; off; off >>= 1) sum += __shfl_xor_sync(0xffffffffu, sum, off);
        float inv = 1.0f / sum;
        #pragma unroll
        for (int q = 0; q < 4; q++) sc[w][lane + 32 * q] = e[q] * inv;
    }
    __syncthreads();

    float az[8][2] = {};
    const int d2 = tid * 2;
    #pragma unroll 4
    for (int s = 0; s < SDIM; s++){
        float2 hv = *(const float2*)(hb + (size_t)s * DDIM + d2);
        #pragma unroll
        for (int tt = 0; tt < 8; tt++){
            float a = sc[tt][s];
            az[tt][0] += a * hv.x;
            az[tt][1] += a * hv.y;
        }
    }
    #pragma unroll
    for (int tt = 0; tt < 8; tt++){
        unsigned hi, lo;
        split2(az[tt][0], az[tt][1], hi, lo);
        size_t off = arow0 + (size_t)tt * 1024 + 512 + d2;
        *(unsigned*)(g_Ah + off) = hi;
        *(unsigned*)(g_Al + off) = lo;
    }
    for (int i = tid; i < 2048; i += 256){
        int tt = i >> 8, q = i & 255;
        float x = s1s[tt][q * 2], y = s1s[tt][q * 2 + 1];
        unsigned hi, lo;
        split2(x, y, hi, lo);
        size_t off = arow0 + (size_t)tt * 1024 + q * 2;
        *(unsigned*)(g_Ah + off) = hi;
        *(unsigned*)(g_Al + off) = lo;
    }
}

// ------------- bf16 hi/lo split of Wout -------------
__global__ void k_cvtW(const float* __restrict__ W){
    const size_t total = (size_t)VSZ * 1024 / 4;
    for (size_t i = (size_t)blockIdx.x * blockDim.x + threadIdx.x; i < total;
         i += (size_t)gridDim.x * blockDim.x){
        float4 v = ((const float4*)W)[i];
        unsigned h0, l0, h1, l1;
        split2(v.x, v.y, h0, l0);
        split2(v.z, v.w, h1, l1);
        ((uint2*)g_Bh)[i] = make_uint2(h0, h1);
        ((uint2*)g_Bl)[i] = make_uint2(l0, l1);
    }
}

// ------------- output GEMM via mma.sync bf16 (3-term split) -------------
#define OST 65536
#define OAH 0
#define OAL 16384
#define OBH 32768
#define OBL 49152

__device__ __forceinline__ uint32_t osw(uint32_t r, uint32_t c8){
    return r * 128u + ((c8 ^ (r & 7u)) * 16u);
}

__global__ void __launch_bounds__(256, 1) k_out_mma(float* __restrict__ out,
                                                    const float* __restrict__ bout){
    extern __shared__ char osm[];
    __shared__ float bias[128];
    const uint32_t sb = smem_u32(osm);
    const int tid = threadIdx.x;
    const int wid = tid >> 5, lane = tid & 31;
    const int wm = wid >> 2, wn = wid & 3;
    const int m0 = blockIdx.x * 128;
    const int n0 = blockIdx.y * 128;

    if (tid < 128) bias[tid] = bout[n0 + tid];

    auto load_chunk = [&](int st, int kc){
        const uint32_t stb = sb + (uint32_t)st * OST;
        #pragma unroll
        for (int q = 0; q < 8; q++){
            int i = tid + q * 256;
            int r = (i & 1023) >> 3, c8 = i & 7;
            const __nv_bfloat16* src = (i < 1024) ? g_Ah : g_Al;
            uint32_t dst = stb + (i < 1024 ? OAH : OAL) + osw((uint32_t)r, (uint32_t)c8);
            CP_ASYNC16(dst, src + (size_t)(m0 + r) * 1024 + kc + c8 * 8);
        }
        #pragma unroll
        for (int q = 0; q < 8; q++){
            int i = tid + q * 256;
            int r = (i & 1023) >> 3, c8 = i & 7;
            const __nv_bfloat16* src = (i < 1024) ? g_Bh : g_Bl;
            uint32_t dst = stb + (i < 1024 ? OBH : OBL) + osw((uint32_t)r, (uint32_t)c8);
            CP_ASYNC16(dst, src + (size_t)(n0 + r) * 1024 + kc + c8 * 8);
        }
        CP_COMMIT();
    };

    float acc[4][4][4] = {};

    load_chunk(0, 0);
    load_chunk(1, 64);
    load_chunk(2, 128);

    #pragma unroll 1
    for (int c = 0; c < 16; c++){
        if      (c < 14) { CP_WAIT(2); }
        else if (c == 14){ CP_WAIT(1); }
        else             { CP_WAIT(0); }
        __syncthreads();

        const uint32_t base = sb + (uint32_t)(c % 3) * OST;
        #pragma unroll
        for (int ks = 0; ks < 4; ks++){
            const int k0 = ks * 16;
            uint32_t Ah[4][4], Al[4][4], Bh[4][2], Bl[4][2];
            {
                uint32_t arow = (uint32_t)(wm * 64 + ((lane >> 3) & 1) * 8 + (lane & 7));
                uint32_t ac8  = (uint32_t)((k0 >> 3) + (lane >> 4));
                #pragma unroll
                for (int f = 0; f < 4; f++){
                    uint32_t off = osw(arow + f * 16, ac8);
                    LDSM4(Ah[f], base + OAH + off);
                    LDSM4(Al[f], base + OAL + off);
                }
            }
            {
                uint32_t brow = (uint32_t)(wn * 32 + (lane & 7));
                uint32_t bc8  = (uint32_t)((k0 >> 3) + ((lane >> 3) & 1));
                #pragma unroll
                for (int g = 0; g < 4; g++){
                    uint32_t off = osw(brow + g * 8, bc8);
                    LDSM2(Bh[g], base + OBH + off);
                    LDSM2(Bl[g], base + OBL + off);
                }
            }
            #pragma unroll
            for (int f = 0; f < 4; f++)
                #pragma unroll
                for (int g = 0; g < 4; g++){
                    MMA_BF16(acc[f][g], Ah[f], Bh[g]);
                    MMA_BF16(acc[f][g], Al[f], Bh[g]);
                    MMA_BF16(acc[f][g], Ah[f], Bl[g]);
                }
        }
        __syncthreads();
        if (c + 3 < 16) load_chunk((c + 3) % 3, (c + 3) * 64);
    }

    const size_t ob = (size_t)blockIdx.x * VSZ * TDIM;
    #pragma unroll
    for (int f = 0; f < 4; f++){
        int m = wm * 64 + f * 16 + (lane >> 2);
        #pragma unroll
        for (int g = 0; g < 4; g++){
            int n = wn * 32 + g * 8 + (lane & 3) * 2;
            float* p = out + ob + (size_t)(n0 + n) * TDIM + m;
            p[0]        = acc[f][g][0] + bias[n];
            p[TDIM]     = acc[f][g][1] + bias[n + 1];
            p[8]        = acc[f][g][2] + bias[n];
            p[8 + TDIM] = acc[f][g][3] + bias[n + 1];
        }
    }
}

// ------------- launcher -------------
extern "C" void kernel_launch(void* const* d_in, const int* in_sizes, int n_in,
                              void* d_out, int out_size){
    const int*   tar  = (const int*)  d_in[0];
    const float* h    = (const float*)d_in[1];
    const float* s0   = (const float*)d_in[2];
    const float* c0   = (const float*)d_in[3];
    const float* emb  = (const float*)d_in[4];
    const float* Wih0 = (const float*)d_in[5];
    const float* Whh0 = (const float*)d_in[6];
    const float* bih0 = (const float*)d_in[7];
    const float* bhh0 = (const float*)d_in[8];
    const float* Wih1 = (const float*)d_in[9];
    const float* Whh1 = (const float*)d_in[10];
    const float* bih1 = (const float*)d_in[11];
    const float* bhh1 = (const float*)d_in[12];
    const float* Wout = (const float*)d_in[13];
    const float* bout = (const float*)d_in[14];
    float* out = (float*)d_out;

    static int attr_set = 0;
    static cudaStream_t s2 = nullptr;
    static cudaEvent_t ev1 = nullptr, ev2 = nullptr;
    if (!attr_set){
        cudaFuncSetAttribute(k_rec, cudaFuncAttributeMaxDynamicSharedMemorySize,
                             (int)sizeof(RecSmem));
        cudaFuncSetAttribute(k_out_mma, cudaFuncAttributeMaxDynamicSharedMemorySize,
                             3 * OST);
        cudaStreamCreateWithFlags(&s2, cudaStreamNonBlocking);
        cudaEventCreateWithFlags(&ev1, cudaEventDisableTiming);
        cudaEventCreateWithFlags(&ev2, cudaEventDisableTiming);
        attr_set = 1;
    }

    // fork: cvtW runs concurrently with the recurrence chain
    cudaEventRecord(ev1, 0);
    cudaStreamWaitEvent(s2, ev1, 0);
    k_cvtW<<<2048, 256, 0, s2>>>(Wout);
    cudaEventRecord(ev2, s2);

    k_init<<<64, 256>>>(s0, c0);
    k_x0<<<dim3(32, 64), 256>>>(tar, emb, Wih0, bih0, bhh0);
    k_rec<<<NCTA, NTHR, sizeof(RecSmem)>>>(c0, Whh0, Wih1, Whh1, bih1, bhh1);
    k_attn2<<<dim3(16, 32), 256>>>(h);

    cudaStreamWaitEvent(0, ev2, 0);
    k_out_mma<<<dim3(32, 250), 256, 3 * OST>>>(out, bout);
}

// round 15
// speedup vs baseline: 1.2538x; 1.1145x over previous
#include <cuda_runtime.h>
#include <cuda_bf16.h>
#include <math.h>
#include <stdint.h>

#define VSZ  32000
#define EDIM 256
#define DDIM 512
#define BDIM 32
#define TDIM 128
#define SDIM 128
#define PADI 3
#define G4D  2048
#define NCTA 128
#define NTHR 256

// ------------- static device scratch -------------
__device__ float g_X0[(size_t)TDIM * BDIM * G4D];
__device__ float g_A [(size_t)BDIM * TDIM * 2 * DDIM];
__device__ float g_s0[2][BDIM * DDIM];
__device__ float g_s1[2][BDIM * DDIM];
__device__ unsigned g_bar_cnt = 0;
__device__ unsigned g_bar_gen = 0;

__device__ __nv_bfloat16 g_Ah[(size_t)4096 * 1024];
__device__ __nv_bfloat16 g_Al[(size_t)4096 * 1024];
__device__ __nv_bfloat16 g_Bh[(size_t)VSZ * 1024];
__device__ __nv_bfloat16 g_Bl[(size_t)VSZ * 1024];

__device__ __forceinline__ float sigf(float x){ return 1.0f / (1.0f + expf(-x)); }

__device__ __forceinline__ uint32_t smem_u32(const void* p){
    uint32_t a;
    asm("{ .reg .u64 t; cvta.to.shared.u64 t, %1; cvt.u32.u64 %0, t; }" : "=r"(a) : "l"(p));
    return a;
}

// ---- packed f32x2 helpers ----
__device__ __forceinline__ unsigned long long splat2(float x){
    unsigned long long u; unsigned r = __float_as_uint(x);
    asm("mov.b64 %0, {%1, %1};" : "=l"(u) : "r"(r));
    return u;
}
__device__ __forceinline__ void ffma2(unsigned long long& d, unsigned long long a, unsigned long long b){
    asm("fma.rn.f32x2 %0, %1, %2, %3;" : "=l"(d) : "l"(a), "l"(b), "l"(d));
}
__device__ __forceinline__ float2 u2f(unsigned long long u){
    float2 r;
    asm("mov.b64 {%0, %1}, %2;" : "=f"(r.x), "=f"(r.y) : "l"(u));
    return r;
}

#define CP_ASYNC16(dst, src) \
    asm volatile("cp.async.cg.shared.global [%0], [%1], 16;" :: "r"(dst), "l"(src))
#define CP_COMMIT() asm volatile("cp.async.commit_group;" ::: "memory")
#define CP_WAIT(n)  asm volatile("cp.async.wait_group %0;" :: "n"(n) : "memory")

#define LDSM4(r, a) \
    asm volatile("ldmatrix.sync.aligned.m8n8.x4.shared.b16 {%0,%1,%2,%3}, [%4];" \
        : "=r"((r)[0]), "=r"((r)[1]), "=r"((r)[2]), "=r"((r)[3]) : "r"(a))
#define LDSM2(r, a) \
    asm volatile("ldmatrix.sync.aligned.m8n8.x2.shared.b16 {%0,%1}, [%2];" \
        : "=r"((r)[0]), "=r"((r)[1]) : "r"(a))
#define MMA_BF16(d, a, b) \
    asm volatile("mma.sync.aligned.m16n8k16.row.col.f32.bf16.bf16.f32 " \
        "{%0,%1,%2,%3}, {%4,%5,%6,%7}, {%8,%9}, {%0,%1,%2,%3};" \
        : "+f"((d)[0]), "+f"((d)[1]), "+f"((d)[2]), "+f"((d)[3]) \
        : "r"((a)[0]), "r"((a)[1]), "r"((a)[2]), "r"((a)[3]), "r"((b)[0]), "r"((b)[1]))

__device__ __forceinline__ void split2(float x, float y, unsigned& hi, unsigned& lo){
    __nv_bfloat16 hx = __float2bfloat16(x), hy = __float2bfloat16(y);
    __nv_bfloat16 lx = __float2bfloat16(x - __bfloat162float(hx));
    __nv_bfloat16 ly = __float2bfloat16(y - __bfloat162float(hy));
    __nv_bfloat162 hp = __halves2bfloat162(hx, hy), lp = __halves2bfloat162(lx, ly);
    hi = *(unsigned*)&hp; lo = *(unsigned*)&lp;
}

// ------------- init recurrent state -------------
__global__ void k_init(const float* __restrict__ s0, const float* __restrict__ c0){
    int i = blockIdx.x * 256 + threadIdx.x;
    if (i < BDIM * DDIM){
        g_s0[0][i] = s0[i];
        g_s1[0][i] = s0[BDIM * DDIM + i];
    }
}

// ------------- X0 = emb_eff[tok] @ Wih0^T + bih0 + bhh0 -------------
__global__ void k_x0(const int* __restrict__ tar, const float* __restrict__ emb,
                     const float* __restrict__ W, const float* __restrict__ b1,
                     const float* __restrict__ b2){
    __shared__ __align__(16) float Ast[32][68];
    __shared__ __align__(16) float Bst[32][68];
    const int tid = threadIdx.x;
    const int n0 = blockIdx.x * 64, m0 = blockIdx.y * 64;
    const int mg = tid >> 4, ng = tid & 15;
    const int ml0 = mg * 4, nl0 = ng * 4;
    const int kl = tid & 31, rl = tid >> 5;
    unsigned long long acc2[2][4];
    #pragma unroll
    for (int i = 0; i < 2; i++)
        #pragma unroll
        for (int j = 0; j < 4; j++) acc2[i][j] = 0ull;

    for (int kc = 0; kc < EDIM; kc += 32){
        #pragma unroll
        for (int l = 0; l < 8; l++){
            int ml = rl + l * 8;
            int m  = m0 + ml;
            int tt = m >> 5, bb = m & 31;
            int tok = tar[bb * TDIM + tt];
            Ast[kl][ml] = (tok == PADI) ? 0.0f : emb[tok * EDIM + kc + kl];
            int nl = rl + l * 8;
            Bst[kl][nl] = W[(n0 + nl) * EDIM + kc + kl];
        }
        __syncthreads();
        #pragma unroll 8
        for (int k = 0; k < 32; k++){
            ulonglong2 ap = *(const ulonglong2*)&Ast[k][ml0];
            float4 bv = *(const float4*)&Bst[k][nl0];
            unsigned long long bs[4] = { splat2(bv.x), splat2(bv.y), splat2(bv.z), splat2(bv.w) };
            #pragma unroll
            for (int j = 0; j < 4; j++){
                ffma2(acc2[0][j], ap.x, bs[j]);
                ffma2(acc2[1][j], ap.y, bs[j]);
            }
        }
        __syncthreads();
    }
    #pragma unroll
    for (int j = 0; j < 4; j++){
        int n = n0 + nl0 + j;
        float bb2 = b1[n] + b2[n];
        float2 p0 = u2f(acc2[0][j]);
        float2 p1 = u2f(acc2[1][j]);
        g_X0[(size_t)(m0 + ml0 + 0) * G4D + n] = p0.x + bb2;
        g_X0[(size_t)(m0 + ml0 + 1) * G4D + n] = p0.y + bb2;
        g_X0[(size_t)(m0 + ml0 + 2) * G4D + n] = p1.x + bb2;
        g_X0[(size_t)(m0 + ml0 + 3) * G4D + n] = p1.y + bb2;
    }
}

// ------------- persistent recurrence kernel: pipelined, 1 barrier/step (R12 exact) -------------
#define W0STR 129
#define W1STR 257
#define SCOL  33

struct RecSmem {
    float4 W0[16 * W0STR];
    float4 W1[16 * W1STR];
    float4 S4[128 * SCOL];
    float  gpart[8 * 16 * SCOL];
    float  csm0[128];
    float  csm1[128];
    float  bsum[16];
    unsigned gen0;
};

__device__ __forceinline__ void gridbar(unsigned target){
    __syncthreads();
    if (threadIdx.x == 0){
        __threadfence();
        unsigned a = atomicAdd(&g_bar_cnt, 1u);
        if (a == NCTA - 1u){
            g_bar_cnt = 0u;
            __threadfence();
            atomicAdd(&g_bar_gen, 1u);
        } else {
            volatile unsigned* p = &g_bar_gen;
            while ((int)(*p - target) < 0) __nanosleep(32);
        }
        __threadfence();
    }
    __syncthreads();
}

__device__ __forceinline__ int scol(int kq, int b){
    return (b + ((kq >> 2) & 6)) & 31;
}

// one 128-row k-slice GEMM: acc2 += W[rows rg,rg+4,rg+8,rg+12][k-slice kw] * S4
__device__ __forceinline__ void gemm_slice(
    unsigned long long (&acc2)[4][4],
    const float4* __restrict__ wbase, int wstr,
    const float4* __restrict__ S4base, int kw, int bg)
{
    #pragma unroll
    for (int kk = 0; kk < 16; kk++){
        const int kq = kw * 16 + kk;
        const int sh = (kq >> 2) & 6;
        ulonglong2 wv[4], sv[4];
        #pragma unroll
        for (int i = 0; i < 4; i++)
            wv[i] = *(const ulonglong2*)(wbase + i * 4 * wstr + kk);
        const float4* srow = S4base + kq * SCOL;
        #pragma unroll
        for (int j = 0; j < 4; j++)
            sv[j] = *(const ulonglong2*)(srow + ((bg + j * 8 + sh) & 31));
        #pragma unroll
        for (int i = 0; i < 4; i++)
            #pragma unroll
            for (int j = 0; j < 4; j++){
                ffma2(acc2[i][j], wv[i].x, sv[j].x);
                ffma2(acc2[i][j], wv[i].y, sv[j].y);
            }
    }
}

__global__ void __launch_bounds__(NTHR, 1) k_rec(
    const float* __restrict__ c0in,
    const float* __restrict__ Whh0,
    const float* __restrict__ Wih1, const float* __restrict__ Whh1,
    const float* __restrict__ bih1, const float* __restrict__ bhh1)
{
    extern __shared__ RecSmem sm[];
    const int tid = threadIdx.x;
    const int d0  = blockIdx.x * 4;
    const int kw  = tid >> 5;
    const int lane = tid & 31;
    const int rg = lane >> 3;
    const int bg = lane & 7;

    if (tid == 0) sm->gen0 = *(volatile unsigned*)&g_bar_gen;
    for (int i = tid; i < 16 * 128; i += NTHR){
        int r_l = i >> 7, kq = i & 127;
        int gr  = (r_l >> 2) * DDIM + d0 + (r_l & 3);
        sm->W0[r_l * W0STR + kq] = *(const float4*)(Whh0 + (size_t)gr * DDIM + kq * 4);
    }
    for (int i = tid; i < 16 * 256; i += NTHR){
        int r_l = i >> 8, kq = i & 255;
        int gr  = (r_l >> 2) * DDIM + d0 + (r_l & 3);
        float4 v;
        if (kq < 128) v = *(const float4*)(Wih1 + (size_t)gr * DDIM + kq * 4);
        else          v = *(const float4*)(Whh1 + (size_t)gr * DDIM + (kq - 128) * 4);
        sm->W1[r_l * W1STR + kq] = v;
    }
    if (tid < 16){
        int gr = (tid >> 2) * DDIM + d0 + (tid & 3);
        sm->bsum[tid] = bih1[gr] + bhh1[gr];
    }
    if (tid < 128){
        int dl = tid >> 5, b = tid & 31;
        sm->csm0[tid] = c0in[b * DDIM + d0 + dl];
        sm->csm1[tid] = c0in[BDIM * DDIM + b * DDIM + d0 + dl];
    }
    __syncthreads();
    const unsigned gen0 = sm->gen0;

    // Pipelined phases: phase p does cell0(p) [p<T] and cell1(p-1) [p>0].
    for (int p = 0; p <= TDIM; p++){
        const bool do_c0 = (p < TDIM);
        const bool do_c1 = (p > 0);

        // ---- stage s0[p] (shared by cell0(p) and cell1(p-1) K-half1) ----
        {
            const float* Sg = g_s0[p & 1];
            for (int i = tid; i < 4096; i += NTHR){
                int b = i >> 7, kq = i & 127;
                sm->S4[kq * SCOL + scol(kq, b)] = ((const float4*)(Sg + b * DDIM))[kq];
            }
        }
        __syncthreads();

        // X0 prefetch for cell0(p)
        float x0v[4] = {0.f, 0.f, 0.f, 0.f};
        if (do_c0 && tid < 128){
            int dl = tid >> 5, b = tid & 31;
            const float* xp = g_X0 + ((size_t)p * BDIM + b) * G4D + d0 + dl;
            #pragma unroll
            for (int q = 0; q < 4; q++) x0v[q] = xp[q * DDIM];
        }

        // cell1(p-1) K-half1 accumulator (lives across the phase)
        unsigned long long acc1[4][4];
        #pragma unroll
        for (int i = 0; i < 4; i++)
            #pragma unroll
            for (int j = 0; j < 4; j++) acc1[i][j] = 0ull;
        if (do_c1)
            gemm_slice(acc1, sm->W1 + rg * W1STR + kw * 16, W1STR, sm->S4, kw, bg);

        // cell0(p) GEMM
        if (do_c0){
            unsigned long long acc0[4][4];
            #pragma unroll
            for (int i = 0; i < 4; i++)
                #pragma unroll
                for (int j = 0; j < 4; j++) acc0[i][j] = 0ull;
            gemm_slice(acc0, sm->W0 + rg * W0STR + kw * 16, W0STR, sm->S4, kw, bg);
            #pragma unroll
            for (int i = 0; i < 4; i++)
                #pragma unroll
                for (int j = 0; j < 4; j++){
                    float2 v = u2f(acc0[i][j]);
                    sm->gpart[(kw * 16 + rg + 4 * i) * SCOL + bg + 8 * j] = v.x + v.y;
                }
        }
        __syncthreads();   // gpart ready; all S4 reads done

        if (do_c0 && tid < 128){
            int dl = tid >> 5, b = tid & 31;
            float gv[4];
            #pragma unroll
            for (int q = 0; q < 4; q++){
                int r_l = q * 4 + dl;
                float s = 0.f;
                #pragma unroll
                for (int w8 = 0; w8 < 8; w8++)
                    s += sm->gpart[(w8 * 16 + r_l) * SCOL + b];
                gv[q] = s + x0v[q];
            }
            float cn = sigf(gv[1]) * sm->csm0[tid] + sigf(gv[0]) * tanhf(gv[2]);
            sm->csm0[tid] = cn;
            g_s0[(p + 1) & 1][b * DDIM + d0 + dl] = sigf(gv[3]) * tanhf(cn);
        }

        if (do_c1){
            // ---- stage s1[p-1], finish cell1 K-half2 ----
            {
                const float* Ss = g_s1[(p + 1) & 1];
                for (int i = tid; i < 4096; i += NTHR){
                    int b = i >> 7, kq = i & 127;
                    sm->S4[kq * SCOL + scol(kq, b)] = ((const float4*)(Ss + b * DDIM))[kq];
                }
            }
            __syncthreads();

            gemm_slice(acc1, sm->W1 + rg * W1STR + 128 + kw * 16, W1STR, sm->S4, kw, bg);
            #pragma unroll
            for (int i = 0; i < 4; i++)
                #pragma unroll
                for (int j = 0; j < 4; j++){
                    float2 v = u2f(acc1[i][j]);
                    sm->gpart[(kw * 16 + rg + 4 * i) * SCOL + bg + 8 * j] = v.x + v.y;
                }
            __syncthreads();

            if (tid < 128){
                int dl = tid >> 5, b = tid & 31;
                float gv[4];
                #pragma unroll
                for (int q = 0; q < 4; q++){
                    int r_l = q * 4 + dl;
                    float s = 0.f;
                    #pragma unroll
                    for (int w8 = 0; w8 < 8; w8++)
                        s += sm->gpart[(w8 * 16 + r_l) * SCOL + b];
                    gv[q] = s + sm->bsum[r_l];
                }
                float cn = sigf(gv[1]) * sm->csm1[tid] + sigf(gv[0]) * tanhf(gv[2]);
                sm->csm1[tid] = cn;
                float sn = sigf(gv[3]) * tanhf(cn);
                g_s1[p & 1][b * DDIM + d0 + dl] = sn;
                g_A[((size_t)b * TDIM + (p - 1)) * (2 * DDIM) + d0 + dl] = sn;
            }
        }

        gridbar(gen0 + p + 1);
    }
}

// ------------- parallel attention + direct bf16-split write -------------
__global__ void __launch_bounds__(256) k_attn2(const float* __restrict__ h){
    __shared__ __align__(16) float s1s[8][516];
    __shared__ float sc[8][132];
    const int b = blockIdx.y, t0 = blockIdx.x * 8;
    const int tid = threadIdx.x, w = tid >> 5, lane = tid & 31;
    const size_t arow0 = ((size_t)b * TDIM + t0) * 1024;

    for (int i = tid; i < 1024; i += 256){
        int tt = i >> 7, q = i & 127;
        *(float4*)&s1s[tt][q * 4] = *(const float4*)(g_A + arow0 + (size_t)tt * 1024 + q * 4);
    }
    __syncthreads();

    const float* hb = h + (size_t)b * SDIM * DDIM;

    for (int j = 0; j < 16; j++){
        int s = w * 16 + j;
        const float4* hr = (const float4*)(hb + (size_t)s * DDIM);
        float4 hv[4];
        #pragma unroll
        for (int q = 0; q < 4; q++) hv[q] = hr[lane + 32 * q];
        float p[8];
        #pragma unroll
        for (int tt = 0; tt < 8; tt++){
            float acc = 0.f;
            #pragma unroll
            for (int q = 0; q < 4; q++){
                float4 sv = *(const float4*)&s1s[tt][(lane + 32 * q) * 4];
                acc += hv[q].x * sv.x + hv[q].y * sv.y + hv[q].z * sv.z + hv[q].w * sv.w;
            }
            p[tt] = acc;
        }
        #pragma unroll
        for (int tt = 0; tt < 8; tt++){
            #pragma unroll
            for (int off = 16; off; off >>= 1)
                p[tt] += __shfl_xor_sync(0xffffffffu, p[tt], off);
        }
        #pragma unroll
        for (int tt = 0; tt < 8; tt++)
            if (lane == tt) sc[tt][s] = p[tt];
    }
    __syncthreads();

    {
        float x[4];
        #pragma unroll
        for (int q = 0; q < 4; q++) x[q] = sc[w][lane + 32 * q];
        float mx = fmaxf(fmaxf(x[0], x[1]), fmaxf(x[2], x[3]));
        #pragma unroll
        for (int off = 16; off; off >>= 1) mx = fmaxf(mx, __shfl_xor_sync(0xffffffffu, mx, off));
        float e[4], sum = 0.f;
        #pragma unroll
        for (int q = 0; q < 4; q++){ e[q] = expf(x[q] - mx); sum += e[q]; }
        #pragma unroll
        for (int off = 16; off; off >>= 1) sum += __shfl_xor_sync(0xffffffffu, sum, off);
        float inv = 1.0f / sum;
        #pragma unroll
        for (int q = 0; q < 4; q++) sc[w][lane + 32 * q] = e[q] * inv;
    }
    __syncthreads();

    float az[8][2] = {};
    const int d2 = tid * 2;
    #pragma unroll 4
    for (int s = 0; s < SDIM; s++){
        float2 hv = *(const float2*)(hb + (size_t)s * DDIM + d2);
        #pragma unroll
        for (int tt = 0; tt < 8; tt++){
            float a = sc[tt][s];
            az[tt][0] += a * hv.x;
            az[tt][1] += a * hv.y;
        }
    }
    #pragma unroll
    for (int tt = 0; tt < 8; tt++){
        unsigned hi, lo;
        split2(az[tt][0], az[tt][1], hi, lo);
        size_t off = arow0 + (size_t)tt * 1024 + 512 + d2;
        *(unsigned*)(g_Ah + off) = hi;
        *(unsigned*)(g_Al + off) = lo;
    }
    for (int i = tid; i < 2048; i += 256){
        int tt = i >> 8, q = i & 255;
        float x = s1s[tt][q * 2], y = s1s[tt][q * 2 + 1];
        unsigned hi, lo;
        split2(x, y, hi, lo);
        size_t off = arow0 + (size_t)tt * 1024 + q * 2;
        *(unsigned*)(g_Ah + off) = hi;
        *(unsigned*)(g_Al + off) = lo;
    }
}

// ------------- bf16 hi/lo split of Wout -------------
__global__ void k_cvtW(const float* __restrict__ W){
    const size_t total = (size_t)VSZ * 1024 / 4;
    for (size_t i = (size_t)blockIdx.x * blockDim.x + threadIdx.x; i < total;
         i += (size_t)gridDim.x * blockDim.x){
        float4 v = ((const float4*)W)[i];
        unsigned h0, l0, h1, l1;
        split2(v.x, v.y, h0, l0);
        split2(v.z, v.w, h1, l1);
        ((uint2*)g_Bh)[i] = make_uint2(h0, h1);
        ((uint2*)g_Bl)[i] = make_uint2(l0, l1);
    }
}

// ------------- output GEMM via mma.sync bf16 (3-term split) -------------
#define OST 65536
#define OAH 0
#define OAL 16384
#define OBH 32768
#define OBL 49152

__device__ __forceinline__ uint32_t osw(uint32_t r, uint32_t c8){
    return r * 128u + ((c8 ^ (r & 7u)) * 16u);
}

__global__ void __launch_bounds__(256, 1) k_out_mma(float* __restrict__ out,
                                                    const float* __restrict__ bout){
    extern __shared__ char osm[];
    __shared__ float bias[128];
    const uint32_t sb = smem_u32(osm);
    const int tid = threadIdx.x;
    const int wid = tid >> 5, lane = tid & 31;
    const int wm = wid >> 2, wn = wid & 3;
    const int m0 = blockIdx.x * 128;
    const int n0 = blockIdx.y * 128;

    if (tid < 128) bias[tid] = bout[n0 + tid];

    auto load_chunk = [&](int st, int kc){
        const uint32_t stb = sb + (uint32_t)st * OST;
        #pragma unroll
        for (int q = 0; q < 8; q++){
            int i = tid + q * 256;
            int r = (i & 1023) >> 3, c8 = i & 7;
            const __nv_bfloat16* src = (i < 1024) ? g_Ah : g_Al;
            uint32_t dst = stb + (i < 1024 ? OAH : OAL) + osw((uint32_t)r, (uint32_t)c8);
            CP_ASYNC16(dst, src + (size_t)(m0 + r) * 1024 + kc + c8 * 8);
        }
        #pragma unroll
        for (int q = 0; q < 8; q++){
            int i = tid + q * 256;
            int r = (i & 1023) >> 3, c8 = i & 7;
            const __nv_bfloat16* src = (i < 1024) ? g_Bh : g_Bl;
            uint32_t dst = stb + (i < 1024 ? OBH : OBL) + osw((uint32_t)r, (uint32_t)c8);
            CP_ASYNC16(dst, src + (size_t)(n0 + r) * 1024 + kc + c8 * 8);
        }
        CP_COMMIT();
    };

    float acc[4][4][4] = {};

    load_chunk(0, 0);
    load_chunk(1, 64);
    load_chunk(2, 128);

    #pragma unroll 1
    for (int c = 0; c < 16; c++){
        if      (c < 14) { CP_WAIT(2); }
        else if (c == 14){ CP_WAIT(1); }
        else             { CP_WAIT(0); }
        __syncthreads();

        const uint32_t base = sb + (uint32_t)(c % 3) * OST;
        #pragma unroll
        for (int ks = 0; ks < 4; ks++){
            const int k0 = ks * 16;
            uint32_t Ah[4][4], Al[4][4], Bh[4][2], Bl[4][2];
            {
                uint32_t arow = (uint32_t)(wm * 64 + ((lane >> 3) & 1) * 8 + (lane & 7));
                uint32_t ac8  = (uint32_t)((k0 >> 3) + (lane >> 4));
                #pragma unroll
                for (int f = 0; f < 4; f++){
                    uint32_t off = osw(arow + f * 16, ac8);
                    LDSM4(Ah[f], base + OAH + off);
                    LDSM4(Al[f], base + OAL + off);
                }
            }
            {
                uint32_t brow = (uint32_t)(wn * 32 + (lane & 7));
                uint32_t bc8  = (uint32_t)((k0 >> 3) + ((lane >> 3) & 1));
                #pragma unroll
                for (int g = 0; g < 4; g++){
                    uint32_t off = osw(brow + g * 8, bc8);
                    LDSM2(Bh[g], base + OBH + off);
                    LDSM2(Bl[g], base + OBL + off);
                }
            }
            #pragma unroll
            for (int f = 0; f < 4; f++)
                #pragma unroll
                for (int g = 0; g < 4; g++){
                    MMA_BF16(acc[f][g], Ah[f], Bh[g]);
                    MMA_BF16(acc[f][g], Al[f], Bh[g]);
                    MMA_BF16(acc[f][g], Ah[f], Bl[g]);
                }
        }
        __syncthreads();
        if (c + 3 < 16) load_chunk((c + 3) % 3, (c + 3) * 64);
    }

    const size_t ob = (size_t)blockIdx.x * VSZ * TDIM;
    #pragma unroll
    for (int f = 0; f < 4; f++){
        int m = wm * 64 + f * 16 + (lane >> 2);
        #pragma unroll
        for (int g = 0; g < 4; g++){
            int n = wn * 32 + g * 8 + (lane & 3) * 2;
            float* p = out + ob + (size_t)(n0 + n) * TDIM + m;
            p[0]        = acc[f][g][0] + bias[n];
            p[TDIM]     = acc[f][g][1] + bias[n + 1];
            p[8]        = acc[f][g][2] + bias[n];
            p[8 + TDIM] = acc[f][g][3] + bias[n + 1];
        }
    }
}

// ------------- launcher -------------
extern "C" void kernel_launch(void* const* d_in, const int* in_sizes, int n_in,
                              void* d_out, int out_size){
    const int*   tar  = (const int*)  d_in[0];
    const float* h    = (const float*)d_in[1];
    const float* s0   = (const float*)d_in[2];
    const float* c0   = (const float*)d_in[3];
    const float* emb  = (const float*)d_in[4];
    const float* Wih0 = (const float*)d_in[5];
    const float* Whh0 = (const float*)d_in[6];
    const float* bih0 = (const float*)d_in[7];
    const float* bhh0 = (const float*)d_in[8];
    const float* Wih1 = (const float*)d_in[9];
    const float* Whh1 = (const float*)d_in[10];
    const float* bih1 = (const float*)d_in[11];
    const float* bhh1 = (const float*)d_in[12];
    const float* Wout = (const float*)d_in[13];
    const float* bout = (const float*)d_in[14];
    float* out = (float*)d_out;

    static int attr_set = 0;
    static cudaStream_t s2 = nullptr;
    static cudaEvent_t ev1 = nullptr, ev2 = nullptr;
    if (!attr_set){
        cudaFuncSetAttribute(k_rec, cudaFuncAttributeMaxDynamicSharedMemorySize,
                             (int)sizeof(RecSmem));
        cudaFuncSetAttribute(k_out_mma, cudaFuncAttributeMaxDynamicSharedMemorySize,
                             3 * OST);
        cudaStreamCreateWithFlags(&s2, cudaStreamNonBlocking);
        cudaEventCreateWithFlags(&ev1, cudaEventDisableTiming);
        cudaEventCreateWithFlags(&ev2, cudaEventDisableTiming);
        attr_set = 1;
    }

    // fork: cvtW (independent until k_out_mma) runs concurrently
    cudaEventRecord(ev1, 0);
    cudaStreamWaitEvent(s2, ev1, 0);
    k_cvtW<<<2048, 256, 0, s2>>>(Wout);
    cudaEventRecord(ev2, s2);

    k_init<<<64, 256>>>(s0, c0);
    k_x0<<<dim3(32, 64), 256>>>(tar, emb, Wih0, bih0, bhh0);
    k_rec<<<NCTA, NTHR, sizeof(RecSmem)>>>(c0, Whh0, Wih1, Whh1, bih1, bhh1);
    k_attn2<<<dim3(16, 32), 256>>>(h);

    cudaStreamWaitEvent(0, ev2, 0);
    k_out_mma<<<dim3(32, 250), 256, 3 * OST>>>(out, bout);
}

// round 16
// speedup vs baseline: 1.2549x; 1.0009x over previous
#include <cuda_runtime.h>
#include <cuda_bf16.h>
#include <math.h>
#include <stdint.h>

#define VSZ  32000
#define EDIM 256
#define DDIM 512
#define BDIM 32
#define TDIM 128
#define SDIM 128
#define PADI 3
#define G4D  2048
#define NCTA 128
#define NTHR 256

// ------------- static device scratch -------------
__device__ float g_X0[(size_t)TDIM * BDIM * G4D];
__device__ float g_A [(size_t)BDIM * TDIM * 2 * DDIM];
__device__ float g_s0[2][BDIM * DDIM];
__device__ float g_s1[2][BDIM * DDIM];
__device__ unsigned g_bar_cnt = 0;
__device__ unsigned g_bar_gen = 0;

__device__ __nv_bfloat16 g_Ah[(size_t)4096 * 1024];
__device__ __nv_bfloat16 g_Al[(size_t)4096 * 1024];
__device__ __nv_bfloat16 g_Bh[(size_t)VSZ * 1024];
__device__ __nv_bfloat16 g_Bl[(size_t)VSZ * 1024];

__device__ __forceinline__ float sigf(float x){ return 1.0f / (1.0f + expf(-x)); }

__device__ __forceinline__ uint32_t smem_u32(const void* p){
    uint32_t a;
    asm("{ .reg .u64 t; cvta.to.shared.u64 t, %1; cvt.u32.u64 %0, t; }" : "=r"(a) : "l"(p));
    return a;
}

// ---- packed f32x2 helpers ----
__device__ __forceinline__ unsigned long long splat2(float x){
    unsigned long long u; unsigned r = __float_as_uint(x);
    asm("mov.b64 %0, {%1, %1};" : "=l"(u) : "r"(r));
    return u;
}
__device__ __forceinline__ void ffma2(unsigned long long& d, unsigned long long a, unsigned long long b){
    asm("fma.rn.f32x2 %0, %1, %2, %3;" : "=l"(d) : "l"(a), "l"(b), "l"(d));
}
__device__ __forceinline__ float2 u2f(unsigned long long u){
    float2 r;
    asm("mov.b64 {%0, %1}, %2;" : "=f"(r.x), "=f"(r.y) : "l"(u));
    return r;
}

#define CP_ASYNC16(dst, src) \
    asm volatile("cp.async.cg.shared.global [%0], [%1], 16;" :: "r"(dst), "l"(src))
#define CP_COMMIT() asm volatile("cp.async.commit_group;" ::: "memory")
#define CP_WAIT(n)  asm volatile("cp.async.wait_group %0;" :: "n"(n) : "memory")

#define LDSM4(r, a) \
    asm volatile("ldmatrix.sync.aligned.m8n8.x4.shared.b16 {%0,%1,%2,%3}, [%4];" \
        : "=r"((r)[0]), "=r"((r)[1]), "=r"((r)[2]), "=r"((r)[3]) : "r"(a))
#define LDSM2(r, a) \
    asm volatile("ldmatrix.sync.aligned.m8n8.x2.shared.b16 {%0,%1}, [%2];" \
        : "=r"((r)[0]), "=r"((r)[1]) : "r"(a))
#define MMA_BF16(d, a, b) \
    asm volatile("mma.sync.aligned.m16n8k16.row.col.f32.bf16.bf16.f32 " \
        "{%0,%1,%2,%3}, {%4,%5,%6,%7}, {%8,%9}, {%0,%1,%2,%3};" \
        : "+f"((d)[0]), "+f"((d)[1]), "+f"((d)[2]), "+f"((d)[3]) \
        : "r"((a)[0]), "r"((a)[1]), "r"((a)[2]), "r"((a)[3]), "r"((b)[0]), "r"((b)[1]))

__device__ __forceinline__ void split2(float x, float y, unsigned& hi, unsigned& lo){
    __nv_bfloat16 hx = __float2bfloat16(x), hy = __float2bfloat16(y);
    __nv_bfloat16 lx = __float2bfloat16(x - __bfloat162float(hx));
    __nv_bfloat16 ly = __float2bfloat16(y - __bfloat162float(hy));
    __nv_bfloat162 hp = __halves2bfloat162(hx, hy), lp = __halves2bfloat162(lx, ly);
    hi = *(unsigned*)&hp; lo = *(unsigned*)&lp;
}

// ------------- init recurrent state -------------
__global__ void k_init(const float* __restrict__ s0, const float* __restrict__ c0){
    int i = blockIdx.x * 256 + threadIdx.x;
    if (i < BDIM * DDIM){
        g_s0[0][i] = s0[i];
        g_s1[0][i] = s0[BDIM * DDIM + i];
    }
}

// ------------- X0 = emb_eff[tok] @ Wih0^T + bih0 + bhh0 -------------
__global__ void k_x0(const int* __restrict__ tar, const float* __restrict__ emb,
                     const float* __restrict__ W, const float* __restrict__ b1,
                     const float* __restrict__ b2){
    __shared__ __align__(16) float Ast[32][68];
    __shared__ __align__(16) float Bst[32][68];
    const int tid = threadIdx.x;
    const int n0 = blockIdx.x * 64, m0 = blockIdx.y * 64;
    const int mg = tid >> 4, ng = tid & 15;
    const int ml0 = mg * 4, nl0 = ng * 4;
    const int kl = tid & 31, rl = tid >> 5;
    unsigned long long acc2[2][4];
    #pragma unroll
    for (int i = 0; i < 2; i++)
        #pragma unroll
        for (int j = 0; j < 4; j++) acc2[i][j] = 0ull;

    for (int kc = 0; kc < EDIM; kc += 32){
        #pragma unroll
        for (int l = 0; l < 8; l++){
            int ml = rl + l * 8;
            int m  = m0 + ml;
            int tt = m >> 5, bb = m & 31;
            int tok = tar[bb * TDIM + tt];
            Ast[kl][ml] = (tok == PADI) ? 0.0f : emb[tok * EDIM + kc + kl];
            int nl = rl + l * 8;
            Bst[kl][nl] = W[(n0 + nl) * EDIM + kc + kl];
        }
        __syncthreads();
        #pragma unroll 8
        for (int k = 0; k < 32; k++){
            ulonglong2 ap = *(const ulonglong2*)&Ast[k][ml0];
            float4 bv = *(const float4*)&Bst[k][nl0];
            unsigned long long bs[4] = { splat2(bv.x), splat2(bv.y), splat2(bv.z), splat2(bv.w) };
            #pragma unroll
            for (int j = 0; j < 4; j++){
                ffma2(acc2[0][j], ap.x, bs[j]);
                ffma2(acc2[1][j], ap.y, bs[j]);
            }
        }
        __syncthreads();
    }
    #pragma unroll
    for (int j = 0; j < 4; j++){
        int n = n0 + nl0 + j;
        float bb2 = b1[n] + b2[n];
        float2 p0 = u2f(acc2[0][j]);
        float2 p1 = u2f(acc2[1][j]);
        g_X0[(size_t)(m0 + ml0 + 0) * G4D + n] = p0.x + bb2;
        g_X0[(size_t)(m0 + ml0 + 1) * G4D + n] = p0.y + bb2;
        g_X0[(size_t)(m0 + ml0 + 2) * G4D + n] = p1.x + bb2;
        g_X0[(size_t)(m0 + ml0 + 3) * G4D + n] = p1.y + bb2;
    }
}

// ------------- persistent recurrence kernel: pipelined, 1 barrier/step (R12 exact) -------------
#define W0STR 129
#define W1STR 257
#define SCOL  33

struct RecSmem {
    float4 W0[16 * W0STR];
    float4 W1[16 * W1STR];
    float4 S4[128 * SCOL];
    float  gpart[8 * 16 * SCOL];
    float  csm0[128];
    float  csm1[128];
    float  bsum[16];
    unsigned gen0;
};

__device__ __forceinline__ void gridbar(unsigned target){
    __syncthreads();
    if (threadIdx.x == 0){
        __threadfence();
        unsigned a = atomicAdd(&g_bar_cnt, 1u);
        if (a == NCTA - 1u){
            g_bar_cnt = 0u;
            __threadfence();
            atomicAdd(&g_bar_gen, 1u);
        } else {
            volatile unsigned* p = &g_bar_gen;
            while ((int)(*p - target) < 0) __nanosleep(32);
        }
        __threadfence();
    }
    __syncthreads();
}

__device__ __forceinline__ int scol(int kq, int b){
    return (b + ((kq >> 2) & 6)) & 31;
}

// one 128-row k-slice GEMM: acc2 += W[rows rg,rg+4,rg+8,rg+12][k-slice kw] * S4
__device__ __forceinline__ void gemm_slice(
    unsigned long long (&acc2)[4][4],
    const float4* __restrict__ wbase, int wstr,
    const float4* __restrict__ S4base, int kw, int bg)
{
    #pragma unroll
    for (int kk = 0; kk < 16; kk++){
        const int kq = kw * 16 + kk;
        const int sh = (kq >> 2) & 6;
        ulonglong2 wv[4], sv[4];
        #pragma unroll
        for (int i = 0; i < 4; i++)
            wv[i] = *(const ulonglong2*)(wbase + i * 4 * wstr + kk);
        const float4* srow = S4base + kq * SCOL;
        #pragma unroll
        for (int j = 0; j < 4; j++)
            sv[j] = *(const ulonglong2*)(srow + ((bg + j * 8 + sh) & 31));
        #pragma unroll
        for (int i = 0; i < 4; i++)
            #pragma unroll
            for (int j = 0; j < 4; j++){
                ffma2(acc2[i][j], wv[i].x, sv[j].x);
                ffma2(acc2[i][j], wv[i].y, sv[j].y);
            }
    }
}

__global__ void __launch_bounds__(NTHR, 1) k_rec(
    const float* __restrict__ c0in,
    const float* __restrict__ Whh0,
    const float* __restrict__ Wih1, const float* __restrict__ Whh1,
    const float* __restrict__ bih1, const float* __restrict__ bhh1)
{
    extern __shared__ RecSmem sm[];
    const int tid = threadIdx.x;
    const int d0  = blockIdx.x * 4;
    const int kw  = tid >> 5;
    const int lane = tid & 31;
    const int rg = lane >> 3;
    const int bg = lane & 7;

    if (tid == 0) sm->gen0 = *(volatile unsigned*)&g_bar_gen;
    for (int i = tid; i < 16 * 128; i += NTHR){
        int r_l = i >> 7, kq = i & 127;
        int gr  = (r_l >> 2) * DDIM + d0 + (r_l & 3);
        sm->W0[r_l * W0STR + kq] = *(const float4*)(Whh0 + (size_t)gr * DDIM + kq * 4);
    }
    for (int i = tid; i < 16 * 256; i += NTHR){
        int r_l = i >> 8, kq = i & 255;
        int gr  = (r_l >> 2) * DDIM + d0 + (r_l & 3);
        float4 v;
        if (kq < 128) v = *(const float4*)(Wih1 + (size_t)gr * DDIM + kq * 4);
        else          v = *(const float4*)(Whh1 + (size_t)gr * DDIM + (kq - 128) * 4);
        sm->W1[r_l * W1STR + kq] = v;
    }
    if (tid < 16){
        int gr = (tid >> 2) * DDIM + d0 + (tid & 3);
        sm->bsum[tid] = bih1[gr] + bhh1[gr];
    }
    if (tid < 128){
        int dl = tid >> 5, b = tid & 31;
        sm->csm0[tid] = c0in[b * DDIM + d0 + dl];
        sm->csm1[tid] = c0in[BDIM * DDIM + b * DDIM + d0 + dl];
    }
    __syncthreads();
    const unsigned gen0 = sm->gen0;

    // Pipelined phases: phase p does cell0(p) [p<T] and cell1(p-1) [p>0].
    for (int p = 0; p <= TDIM; p++){
        const bool do_c0 = (p < TDIM);
        const bool do_c1 = (p > 0);

        // ---- stage s0[p] (shared by cell0(p) and cell1(p-1) K-half1) ----
        {
            const float* Sg = g_s0[p & 1];
            for (int i = tid; i < 4096; i += NTHR){
                int b = i >> 7, kq = i & 127;
                sm->S4[kq * SCOL + scol(kq, b)] = ((const float4*)(Sg + b * DDIM))[kq];
            }
        }
        __syncthreads();

        // X0 prefetch for cell0(p)
        float x0v[4] = {0.f, 0.f, 0.f, 0.f};
        if (do_c0 && tid < 128){
            int dl = tid >> 5, b = tid & 31;
            const float* xp = g_X0 + ((size_t)p * BDIM + b) * G4D + d0 + dl;
            #pragma unroll
            for (int q = 0; q < 4; q++) x0v[q] = xp[q * DDIM];
        }

        // cell1(p-1) K-half1 accumulator (lives across the phase)
        unsigned long long acc1[4][4];
        #pragma unroll
        for (int i = 0; i < 4; i++)
            #pragma unroll
            for (int j = 0; j < 4; j++) acc1[i][j] = 0ull;
        if (do_c1)
            gemm_slice(acc1, sm->W1 + rg * W1STR + kw * 16, W1STR, sm->S4, kw, bg);

        // cell0(p) GEMM
        if (do_c0){
            unsigned long long acc0[4][4];
            #pragma unroll
            for (int i = 0; i < 4; i++)
                #pragma unroll
                for (int j = 0; j < 4; j++) acc0[i][j] = 0ull;
            gemm_slice(acc0, sm->W0 + rg * W0STR + kw * 16, W0STR, sm->S4, kw, bg);
            #pragma unroll
            for (int i = 0; i < 4; i++)
                #pragma unroll
                for (int j = 0; j < 4; j++){
                    float2 v = u2f(acc0[i][j]);
                    sm->gpart[(kw * 16 + rg + 4 * i) * SCOL + bg + 8 * j] = v.x + v.y;
                }
        }
        __syncthreads();   // gpart ready; all S4 reads done

        if (do_c0 && tid < 128){
            int dl = tid >> 5, b = tid & 31;
            float gv[4];
            #pragma unroll
            for (int q = 0; q < 4; q++){
                int r_l = q * 4 + dl;
                float s = 0.f;
                #pragma unroll
                for (int w8 = 0; w8 < 8; w8++)
                    s += sm->gpart[(w8 * 16 + r_l) * SCOL + b];
                gv[q] = s + x0v[q];
            }
            float cn = sigf(gv[1]) * sm->csm0[tid] + sigf(gv[0]) * tanhf(gv[2]);
            sm->csm0[tid] = cn;
            g_s0[(p + 1) & 1][b * DDIM + d0 + dl] = sigf(gv[3]) * tanhf(cn);
        }

        if (do_c1){
            // ---- stage s1[p-1], finish cell1 K-half2 ----
            {
                const float* Ss = g_s1[(p + 1) & 1];
                for (int i = tid; i < 4096; i += NTHR){
                    int b = i >> 7, kq = i & 127;
                    sm->S4[kq * SCOL + scol(kq, b)] = ((const float4*)(Ss + b * DDIM))[kq];
                }
            }
            __syncthreads();

            gemm_slice(acc1, sm->W1 + rg * W1STR + 128 + kw * 16, W1STR, sm->S4, kw, bg);
            #pragma unroll
            for (int i = 0; i < 4; i++)
                #pragma unroll
                for (int j = 0; j < 4; j++){
                    float2 v = u2f(acc1[i][j]);
                    sm->gpart[(kw * 16 + rg + 4 * i) * SCOL + bg + 8 * j] = v.x + v.y;
                }
            __syncthreads();

            if (tid < 128){
                int dl = tid >> 5, b = tid & 31;
                float gv[4];
                #pragma unroll
                for (int q = 0; q < 4; q++){
                    int r_l = q * 4 + dl;
                    float s = 0.f;
                    #pragma unroll
                    for (int w8 = 0; w8 < 8; w8++)
                        s += sm->gpart[(w8 * 16 + r_l) * SCOL + b];
                    gv[q] = s + sm->bsum[r_l];
                }
                float cn = sigf(gv[1]) * sm->csm1[tid] + sigf(gv[0]) * tanhf(gv[2]);
                sm->csm1[tid] = cn;
                float sn = sigf(gv[3]) * tanhf(cn);
                g_s1[p & 1][b * DDIM + d0 + dl] = sn;
                g_A[((size_t)b * TDIM + (p - 1)) * (2 * DDIM) + d0 + dl] = sn;
            }
        }

        gridbar(gen0 + p + 1);
    }
}

// ------------- parallel attention + direct bf16-split write -------------
__global__ void __launch_bounds__(256) k_attn2(const float* __restrict__ h){
    __shared__ __align__(16) float s1s[8][516];
    __shared__ float sc[8][132];
    const int b = blockIdx.y, t0 = blockIdx.x * 8;
    const int tid = threadIdx.x, w = tid >> 5, lane = tid & 31;
    const size_t arow0 = ((size_t)b * TDIM + t0) * 1024;

    for (int i = tid; i < 1024; i += 256){
        int tt = i >> 7, q = i & 127;
        *(float4*)&s1s[tt][q * 4] = *(const float4*)(g_A + arow0 + (size_t)tt * 1024 + q * 4);
    }
    __syncthreads();

    const float* hb = h + (size_t)b * SDIM * DDIM;

    for (int j = 0; j < 16; j++){
        int s = w * 16 + j;
        const float4* hr = (const float4*)(hb + (size_t)s * DDIM);
        float4 hv[4];
        #pragma unroll
        for (int q = 0; q < 4; q++) hv[q] = hr[lane + 32 * q];
        float p[8];
        #pragma unroll
        for (int tt = 0; tt < 8; tt++){
            float acc = 0.f;
            #pragma unroll
            for (int q = 0; q < 4; q++){
                float4 sv = *(const float4*)&s1s[tt][(lane + 32 * q) * 4];
                acc += hv[q].x * sv.x + hv[q].y * sv.y + hv[q].z * sv.z + hv[q].w * sv.w;
            }
            p[tt] = acc;
        }
        #pragma unroll
        for (int tt = 0; tt < 8; tt++){
            #pragma unroll
            for (int off = 16; off; off >>= 1)
                p[tt] += __shfl_xor_sync(0xffffffffu, p[tt], off);
        }
        #pragma unroll
        for (int tt = 0; tt < 8; tt++)
            if (lane == tt) sc[tt][s] = p[tt];
    }
    __syncthreads();

    {
        float x[4];
        #pragma unroll
        for (int q = 0; q < 4; q++) x[q] = sc[w][lane + 32 * q];
        float mx = fmaxf(fmaxf(x[0], x[1]), fmaxf(x[2], x[3]));
        #pragma unroll
        for (int off = 16; off; off >>= 1) mx = fmaxf(mx, __shfl_xor_sync(0xffffffffu, mx, off));
        float e[4], sum = 0.f;
        #pragma unroll
        for (int q = 0; q < 4; q++){ e[q] = expf(x[q] - mx); sum += e[q]; }
        #pragma unroll
        for (int off = 16; off; off >>= 1) sum += __shfl_xor_sync(0xffffffffu, sum, off);
        float inv = 1.0f / sum;
        #pragma unroll
        for (int q = 0; q < 4; q++) sc[w][lane + 32 * q] = e[q] * inv;
    }
    __syncthreads();

    float az[8][2] = {};
    const int d2 = tid * 2;
    #pragma unroll 4
    for (int s = 0; s < SDIM; s++){
        float2 hv = *(const float2*)(hb + (size_t)s * DDIM + d2);
        #pragma unroll
        for (int tt = 0; tt < 8; tt++){
            float a = sc[tt][s];
            az[tt][0] += a * hv.x;
            az[tt][1] += a * hv.y;
        }
    }
    #pragma unroll
    for (int tt = 0; tt < 8; tt++){
        unsigned hi, lo;
        split2(az[tt][0], az[tt][1], hi, lo);
        size_t off = arow0 + (size_t)tt * 1024 + 512 + d2;
        *(unsigned*)(g_Ah + off) = hi;
        *(unsigned*)(g_Al + off) = lo;
    }
    for (int i = tid; i < 2048; i += 256){
        int tt = i >> 8, q = i & 255;
        float x = s1s[tt][q * 2], y = s1s[tt][q * 2 + 1];
        unsigned hi, lo;
        split2(x, y, hi, lo);
        size_t off = arow0 + (size_t)tt * 1024 + q * 2;
        *(unsigned*)(g_Ah + off) = hi;
        *(unsigned*)(g_Al + off) = lo;
    }
}

// ------------- bf16 hi/lo split of Wout -------------
__global__ void k_cvtW(const float* __restrict__ W){
    const size_t total = (size_t)VSZ * 1024 / 4;
    for (size_t i = (size_t)blockIdx.x * blockDim.x + threadIdx.x; i < total;
         i += (size_t)gridDim.x * blockDim.x){
        float4 v = ((const float4*)W)[i];
        unsigned h0, l0, h1, l1;
        split2(v.x, v.y, h0, l0);
        split2(v.z, v.w, h1, l1);
        ((uint2*)g_Bh)[i] = make_uint2(h0, h1);
        ((uint2*)g_Bl)[i] = make_uint2(l0, l1);
    }
}

// ------------- output GEMM via mma.sync bf16 (3-term split) -------------
#define OST 65536
#define OAH 0
#define OAL 16384
#define OBH 32768
#define OBL 49152

__device__ __forceinline__ uint32_t osw(uint32_t r, uint32_t c8){
    return r * 128u + ((c8 ^ (r & 7u)) * 16u);
}

__global__ void __launch_bounds__(256, 1) k_out_mma(float* __restrict__ out,
                                                    const float* __restrict__ bout){
    extern __shared__ char osm[];
    __shared__ float bias[128];
    const uint32_t sb = smem_u32(osm);
    const int tid = threadIdx.x;
    const int wid = tid >> 5, lane = tid & 31;
    const int wm = wid >> 2, wn = wid & 3;
    const int m0 = blockIdx.x * 128;
    const int n0 = blockIdx.y * 128;

    if (tid < 128) bias[tid] = bout[n0 + tid];

    auto load_chunk = [&](int st, int kc){
        const uint32_t stb = sb + (uint32_t)st * OST;
        #pragma unroll
        for (int q = 0; q < 8; q++){
            int i = tid + q * 256;
            int r = (i & 1023) >> 3, c8 = i & 7;
            const __nv_bfloat16* src = (i < 1024) ? g_Ah : g_Al;
            uint32_t dst = stb + (i < 1024 ? OAH : OAL) + osw((uint32_t)r, (uint32_t)c8);
            CP_ASYNC16(dst, src + (size_t)(m0 + r) * 1024 + kc + c8 * 8);
        }
        #pragma unroll
        for (int q = 0; q < 8; q++){
            int i = tid + q * 256;
            int r = (i & 1023) >> 3, c8 = i & 7;
            const __nv_bfloat16* src = (i < 1024) ? g_Bh : g_Bl;
            uint32_t dst = stb + (i < 1024 ? OBH : OBL) + osw((uint32_t)r, (uint32_t)c8);
            CP_ASYNC16(dst, src + (size_t)(n0 + r) * 1024 + kc + c8 * 8);
        }
        CP_COMMIT();
    };

    float acc[4][4][4] = {};

    load_chunk(0, 0);
    load_chunk(1, 64);
    load_chunk(2, 128);

    #pragma unroll 1
    for (int c = 0; c < 16; c++){
        if      (c < 14) { CP_WAIT(2); }
        else if (c == 14){ CP_WAIT(1); }
        else             { CP_WAIT(0); }
        __syncthreads();

        const uint32_t base = sb + (uint32_t)(c % 3) * OST;
        #pragma unroll
        for (int ks = 0; ks < 4; ks++){
            const int k0 = ks * 16;
            uint32_t Ah[4][4], Al[4][4], Bh[4][2], Bl[4][2];
            {
                uint32_t arow = (uint32_t)(wm * 64 + ((lane >> 3) & 1) * 8 + (lane & 7));
                uint32_t ac8  = (uint32_t)((k0 >> 3) + (lane >> 4));
                #pragma unroll
                for (int f = 0; f < 4; f++){
                    uint32_t off = osw(arow + f * 16, ac8);
                    LDSM4(Ah[f], base + OAH + off);
                    LDSM4(Al[f], base + OAL + off);
                }
            }
            {
                uint32_t brow = (uint32_t)(wn * 32 + (lane & 7));
                uint32_t bc8  = (uint32_t)((k0 >> 3) + ((lane >> 3) & 1));
                #pragma unroll
                for (int g = 0; g < 4; g++){
                    uint32_t off = osw(brow + g * 8, bc8);
                    LDSM2(Bh[g], base + OBH + off);
                    LDSM2(Bl[g], base + OBL + off);
                }
            }
            #pragma unroll
            for (int f = 0; f < 4; f++)
                #pragma unroll
                for (int g = 0; g < 4; g++){
                    MMA_BF16(acc[f][g], Ah[f], Bh[g]);
                    MMA_BF16(acc[f][g], Al[f], Bh[g]);
                    MMA_BF16(acc[f][g], Ah[f], Bl[g]);
                }
        }
        __syncthreads();
        if (c + 3 < 16) load_chunk((c + 3) % 3, (c + 3) * 64);
    }

    const size_t ob = (size_t)blockIdx.x * VSZ * TDIM;
    #pragma unroll
    for (int f = 0; f < 4; f++){
        int m = wm * 64 + f * 16 + (lane >> 2);
        #pragma unroll
        for (int g = 0; g < 4; g++){
            int n = wn * 32 + g * 8 + (lane & 3) * 2;
            float* p = out + ob + (size_t)(n0 + n) * TDIM + m;
            p[0]        = acc[f][g][0] + bias[n];
            p[TDIM]     = acc[f][g][1] + bias[n + 1];
            p[8]        = acc[f][g][2] + bias[n];
            p[8 + TDIM] = acc[f][g][3] + bias[n + 1];
        }
    }
}

// ------------- launcher -------------
extern "C" void kernel_launch(void* const* d_in, const int* in_sizes, int n_in,
                              void* d_out, int out_size){
    const int*   tar  = (const int*)  d_in[0];
    const float* h    = (const float*)d_in[1];
    const float* s0   = (const float*)d_in[2];
    const float* c0   = (const float*)d_in[3];
    const float* emb  = (const float*)d_in[4];
    const float* Wih0 = (const float*)d_in[5];
    const float* Whh0 = (const float*)d_in[6];
    const float* bih0 = (const float*)d_in[7];
    const float* bhh0 = (const float*)d_in[8];
    const float* Wih1 = (const float*)d_in[9];
    const float* Whh1 = (const float*)d_in[10];
    const float* bih1 = (const float*)d_in[11];
    const float* bhh1 = (const float*)d_in[12];
    const float* Wout = (const float*)d_in[13];
    const float* bout = (const float*)d_in[14];
    float* out = (float*)d_out;

    static int attr_set = 0;
    static cudaStream_t s2 = nullptr;
    static cudaEvent_t ev1 = nullptr, ev2 = nullptr;
    if (!attr_set){
        cudaFuncSetAttribute(k_rec, cudaFuncAttributeMaxDynamicSharedMemorySize,
                             (int)sizeof(RecSmem));
        cudaFuncSetAttribute(k_out_mma, cudaFuncAttributeMaxDynamicSharedMemorySize,
                             3 * OST);
        cudaStreamCreateWithFlags(&s2, cudaStreamNonBlocking);
        cudaEventCreateWithFlags(&ev1, cudaEventDisableTiming);
        cudaEventCreateWithFlags(&ev2, cudaEventDisableTiming);
        attr_set = 1;
    }

    // fork: cvtW (independent until k_out_mma) runs concurrently
    cudaEventRecord(ev1, 0);
    cudaStreamWaitEvent(s2, ev1, 0);
    k_cvtW<<<2048, 256, 0, s2>>>(Wout);
    cudaEventRecord(ev2, s2);

    k_init<<<64, 256>>>(s0, c0);
    k_x0<<<dim3(32, 64), 256>>>(tar, emb, Wih0, bih0, bhh0);
    k_rec<<<NCTA, NTHR, sizeof(RecSmem)>>>(c0, Whh0, Wih1, Whh1, bih1, bhh1);
    k_attn2<<<dim3(16, 32), 256>>>(h);

    cudaStreamWaitEvent(0, ev2, 0);
    k_out_mma<<<dim3(32, 250), 256, 3 * OST>>>(out, bout);
}

// round 17
// speedup vs baseline: 1.2561x; 1.0010x over previous
#include <cuda_runtime.h>
#include <cuda_bf16.h>
#include <math.h>
#include <stdint.h>

#define VSZ  32000
#define EDIM 256
#define DDIM 512
#define BDIM 32
#define TDIM 128
#define SDIM 128
#define PADI 3
#define G4D  2048
#define NCTA 128
#define NTHR 256

// ------------- static device scratch -------------
__device__ float g_X0[(size_t)TDIM * BDIM * G4D];
__device__ float g_A [(size_t)BDIM * TDIM * 2 * DDIM];
__device__ float g_s0[2][BDIM * DDIM];
__device__ float g_s1[2][BDIM * DDIM];
__device__ unsigned g_bar_cnt = 0;
__device__ unsigned g_bar_gen = 0;

__device__ __nv_bfloat16 g_Ah[(size_t)4096 * 1024];
__device__ __nv_bfloat16 g_Al[(size_t)4096 * 1024];
__device__ __nv_bfloat16 g_Bh[(size_t)VSZ * 1024];
__device__ __nv_bfloat16 g_Bl[(size_t)VSZ * 1024];

__device__ __forceinline__ float sigf(float x){ return 1.0f / (1.0f + expf(-x)); }

__device__ __forceinline__ uint32_t smem_u32(const void* p){
    uint32_t a;
    asm("{ .reg .u64 t; cvta.to.shared.u64 t, %1; cvt.u32.u64 %0, t; }" : "=r"(a) : "l"(p));
    return a;
}

// ---- packed f32x2 helpers ----
__device__ __forceinline__ unsigned long long splat2(float x){
    unsigned long long u; unsigned r = __float_as_uint(x);
    asm("mov.b64 %0, {%1, %1};" : "=l"(u) : "r"(r));
    return u;
}
__device__ __forceinline__ void ffma2(unsigned long long& d, unsigned long long a, unsigned long long b){
    asm("fma.rn.f32x2 %0, %1, %2, %3;" : "=l"(d) : "l"(a), "l"(b), "l"(d));
}
__device__ __forceinline__ float2 u2f(unsigned long long u){
    float2 r;
    asm("mov.b64 {%0, %1}, %2;" : "=f"(r.x), "=f"(r.y) : "l"(u));
    return r;
}

#define CP_ASYNC16(dst, src) \
    asm volatile("cp.async.cg.shared.global [%0], [%1], 16;" :: "r"(dst), "l"(src))
#define CP_COMMIT() asm volatile("cp.async.commit_group;" ::: "memory")
#define CP_WAIT(n)  asm volatile("cp.async.wait_group %0;" :: "n"(n) : "memory")

#define LDSM4(r, a) \
    asm volatile("ldmatrix.sync.aligned.m8n8.x4.shared.b16 {%0,%1,%2,%3}, [%4];" \
        : "=r"((r)[0]), "=r"((r)[1]), "=r"((r)[2]), "=r"((r)[3]) : "r"(a))
#define LDSM2(r, a) \
    asm volatile("ldmatrix.sync.aligned.m8n8.x2.shared.b16 {%0,%1}, [%2];" \
        : "=r"((r)[0]), "=r"((r)[1]) : "r"(a))
#define MMA_BF16(d, a, b) \
    asm volatile("mma.sync.aligned.m16n8k16.row.col.f32.bf16.bf16.f32 " \
        "{%0,%1,%2,%3}, {%4,%5,%6,%7}, {%8,%9}, {%0,%1,%2,%3};" \
        : "+f"((d)[0]), "+f"((d)[1]), "+f"((d)[2]), "+f"((d)[3]) \
        : "r"((a)[0]), "r"((a)[1]), "r"((a)[2]), "r"((a)[3]), "r"((b)[0]), "r"((b)[1]))

__device__ __forceinline__ void split2(float x, float y, unsigned& hi, unsigned& lo){
    __nv_bfloat16 hx = __float2bfloat16(x), hy = __float2bfloat16(y);
    __nv_bfloat16 lx = __float2bfloat16(x - __bfloat162float(hx));
    __nv_bfloat16 ly = __float2bfloat16(y - __bfloat162float(hy));
    __nv_bfloat162 hp = __halves2bfloat162(hx, hy), lp = __halves2bfloat162(lx, ly);
    hi = *(unsigned*)&hp; lo = *(unsigned*)&lp;
}

// ------------- init recurrent state -------------
__global__ void k_init(const float* __restrict__ s0, const float* __restrict__ c0){
    int i = blockIdx.x * 256 + threadIdx.x;
    if (i < BDIM * DDIM){
        g_s0[0][i] = s0[i];
        g_s1[0][i] = s0[BDIM * DDIM + i];
    }
}

// ------------- X0 = emb_eff[tok] @ Wih0^T + bih0 + bhh0 -------------
__global__ void k_x0(const int* __restrict__ tar, const float* __restrict__ emb,
                     const float* __restrict__ W, const float* __restrict__ b1,
                     const float* __restrict__ b2){
    __shared__ __align__(16) float Ast[32][68];
    __shared__ __align__(16) float Bst[32][68];
    const int tid = threadIdx.x;
    const int n0 = blockIdx.x * 64, m0 = blockIdx.y * 64;
    const int mg = tid >> 4, ng = tid & 15;
    const int ml0 = mg * 4, nl0 = ng * 4;
    const int kl = tid & 31, rl = tid >> 5;
    unsigned long long acc2[2][4];
    #pragma unroll
    for (int i = 0; i < 2; i++)
        #pragma unroll
        for (int j = 0; j < 4; j++) acc2[i][j] = 0ull;

    for (int kc = 0; kc < EDIM; kc += 32){
        #pragma unroll
        for (int l = 0; l < 8; l++){
            int ml = rl + l * 8;
            int m  = m0 + ml;
            int tt = m >> 5, bb = m & 31;
            int tok = tar[bb * TDIM + tt];
            Ast[kl][ml] = (tok == PADI) ? 0.0f : emb[tok * EDIM + kc + kl];
            int nl = rl + l * 8;
            Bst[kl][nl] = W[(n0 + nl) * EDIM + kc + kl];
        }
        __syncthreads();
        #pragma unroll 8
        for (int k = 0; k < 32; k++){
            ulonglong2 ap = *(const ulonglong2*)&Ast[k][ml0];
            float4 bv = *(const float4*)&Bst[k][nl0];
            unsigned long long bs[4] = { splat2(bv.x), splat2(bv.y), splat2(bv.z), splat2(bv.w) };
            #pragma unroll
            for (int j = 0; j < 4; j++){
                ffma2(acc2[0][j], ap.x, bs[j]);
                ffma2(acc2[1][j], ap.y, bs[j]);
            }
        }
        __syncthreads();
    }
    #pragma unroll
    for (int j = 0; j < 4; j++){
        int n = n0 + nl0 + j;
        float bb2 = b1[n] + b2[n];
        float2 p0 = u2f(acc2[0][j]);
        float2 p1 = u2f(acc2[1][j]);
        g_X0[(size_t)(m0 + ml0 + 0) * G4D + n] = p0.x + bb2;
        g_X0[(size_t)(m0 + ml0 + 1) * G4D + n] = p0.y + bb2;
        g_X0[(size_t)(m0 + ml0 + 2) * G4D + n] = p1.x + bb2;
        g_X0[(size_t)(m0 + ml0 + 3) * G4D + n] = p1.y + bb2;
    }
}

// ------------- persistent recurrence kernel: pipelined, 1 barrier/step (R12 exact) -------------
#define W0STR 129
#define W1STR 257
#define SCOL  33

struct RecSmem {
    float4 W0[16 * W0STR];
    float4 W1[16 * W1STR];
    float4 S4[128 * SCOL];
    float  gpart[8 * 16 * SCOL];
    float  csm0[128];
    float  csm1[128];
    float  bsum[16];
    unsigned gen0;
};

__device__ __forceinline__ void gridbar(unsigned target){
    __syncthreads();
    if (threadIdx.x == 0){
        __threadfence();
        unsigned a = atomicAdd(&g_bar_cnt, 1u);
        if (a == NCTA - 1u){
            g_bar_cnt = 0u;
            __threadfence();
            atomicAdd(&g_bar_gen, 1u);
        } else {
            volatile unsigned* p = &g_bar_gen;
            while ((int)(*p - target) < 0) __nanosleep(32);
        }
        __threadfence();
    }
    __syncthreads();
}

__device__ __forceinline__ int scol(int kq, int b){
    return (b + ((kq >> 2) & 6)) & 31;
}

// one 128-row k-slice GEMM: acc2 += W[rows rg,rg+4,rg+8,rg+12][k-slice kw] * S4
__device__ __forceinline__ void gemm_slice(
    unsigned long long (&acc2)[4][4],
    const float4* __restrict__ wbase, int wstr,
    const float4* __restrict__ S4base, int kw, int bg)
{
    #pragma unroll
    for (int kk = 0; kk < 16; kk++){
        const int kq = kw * 16 + kk;
        const int sh = (kq >> 2) & 6;
        ulonglong2 wv[4], sv[4];
        #pragma unroll
        for (int i = 0; i < 4; i++)
            wv[i] = *(const ulonglong2*)(wbase + i * 4 * wstr + kk);
        const float4* srow = S4base + kq * SCOL;
        #pragma unroll
        for (int j = 0; j < 4; j++)
            sv[j] = *(const ulonglong2*)(srow + ((bg + j * 8 + sh) & 31));
        #pragma unroll
        for (int i = 0; i < 4; i++)
            #pragma unroll
            for (int j = 0; j < 4; j++){
                ffma2(acc2[i][j], wv[i].x, sv[j].x);
                ffma2(acc2[i][j], wv[i].y, sv[j].y);
            }
    }
}

__global__ void __launch_bounds__(NTHR, 1) k_rec(
    const float* __restrict__ c0in,
    const float* __restrict__ Whh0,
    const float* __restrict__ Wih1, const float* __restrict__ Whh1,
    const float* __restrict__ bih1, const float* __restrict__ bhh1)
{
    extern __shared__ RecSmem sm[];
    const int tid = threadIdx.x;
    const int d0  = blockIdx.x * 4;
    const int kw  = tid >> 5;
    const int lane = tid & 31;
    const int rg = lane >> 3;
    const int bg = lane & 7;

    if (tid == 0) sm->gen0 = *(volatile unsigned*)&g_bar_gen;
    for (int i = tid; i < 16 * 128; i += NTHR){
        int r_l = i >> 7, kq = i & 127;
        int gr  = (r_l >> 2) * DDIM + d0 + (r_l & 3);
        sm->W0[r_l * W0STR + kq] = *(const float4*)(Whh0 + (size_t)gr * DDIM + kq * 4);
    }
    for (int i = tid; i < 16 * 256; i += NTHR){
        int r_l = i >> 8, kq = i & 255;
        int gr  = (r_l >> 2) * DDIM + d0 + (r_l & 3);
        float4 v;
        if (kq < 128) v = *(const float4*)(Wih1 + (size_t)gr * DDIM + kq * 4);
        else          v = *(const float4*)(Whh1 + (size_t)gr * DDIM + (kq - 128) * 4);
        sm->W1[r_l * W1STR + kq] = v;
    }
    if (tid < 16){
        int gr = (tid >> 2) * DDIM + d0 + (tid & 3);
        sm->bsum[tid] = bih1[gr] + bhh1[gr];
    }
    if (tid < 128){
        int dl = tid >> 5, b = tid & 31;
        sm->csm0[tid] = c0in[b * DDIM + d0 + dl];
        sm->csm1[tid] = c0in[BDIM * DDIM + b * DDIM + d0 + dl];
    }
    __syncthreads();
    const unsigned gen0 = sm->gen0;

    // Pipelined phases: phase p does cell0(p) [p<T] and cell1(p-1) [p>0].
    for (int p = 0; p <= TDIM; p++){
        const bool do_c0 = (p < TDIM);
        const bool do_c1 = (p > 0);

        // ---- stage s0[p] (shared by cell0(p) and cell1(p-1) K-half1) ----
        {
            const float* Sg = g_s0[p & 1];
            for (int i = tid; i < 4096; i += NTHR){
                int b = i >> 7, kq = i & 127;
                sm->S4[kq * SCOL + scol(kq, b)] = ((const float4*)(Sg + b * DDIM))[kq];
            }
        }
        __syncthreads();

        // X0 prefetch for cell0(p)
        float x0v[4] = {0.f, 0.f, 0.f, 0.f};
        if (do_c0 && tid < 128){
            int dl = tid >> 5, b = tid & 31;
            const float* xp = g_X0 + ((size_t)p * BDIM + b) * G4D + d0 + dl;
            #pragma unroll
            for (int q = 0; q < 4; q++) x0v[q] = xp[q * DDIM];
        }

        // cell1(p-1) K-half1 accumulator (lives across the phase)
        unsigned long long acc1[4][4];
        #pragma unroll
        for (int i = 0; i < 4; i++)
            #pragma unroll
            for (int j = 0; j < 4; j++) acc1[i][j] = 0ull;
        if (do_c1)
            gemm_slice(acc1, sm->W1 + rg * W1STR + kw * 16, W1STR, sm->S4, kw, bg);

        // cell0(p) GEMM
        if (do_c0){
            unsigned long long acc0[4][4];
            #pragma unroll
            for (int i = 0; i < 4; i++)
                #pragma unroll
                for (int j = 0; j < 4; j++) acc0[i][j] = 0ull;
            gemm_slice(acc0, sm->W0 + rg * W0STR + kw * 16, W0STR, sm->S4, kw, bg);
            #pragma unroll
            for (int i = 0; i < 4; i++)
                #pragma unroll
                for (int j = 0; j < 4; j++){
                    float2 v = u2f(acc0[i][j]);
                    sm->gpart[(kw * 16 + rg + 4 * i) * SCOL + bg + 8 * j] = v.x + v.y;
                }
        }
        __syncthreads();   // gpart ready; all S4 reads done

        if (do_c0 && tid < 128){
            int dl = tid >> 5, b = tid & 31;
            float gv[4];
            #pragma unroll
            for (int q = 0; q < 4; q++){
                int r_l = q * 4 + dl;
                float s = 0.f;
                #pragma unroll
                for (int w8 = 0; w8 < 8; w8++)
                    s += sm->gpart[(w8 * 16 + r_l) * SCOL + b];
                gv[q] = s + x0v[q];
            }
            float cn = sigf(gv[1]) * sm->csm0[tid] + sigf(gv[0]) * tanhf(gv[2]);
            sm->csm0[tid] = cn;
            g_s0[(p + 1) & 1][b * DDIM + d0 + dl] = sigf(gv[3]) * tanhf(cn);
        }

        if (do_c1){
            // ---- stage s1[p-1], finish cell1 K-half2 ----
            {
                const float* Ss = g_s1[(p + 1) & 1];
                for (int i = tid; i < 4096; i += NTHR){
                    int b = i >> 7, kq = i & 127;
                    sm->S4[kq * SCOL + scol(kq, b)] = ((const float4*)(Ss + b * DDIM))[kq];
                }
            }
            __syncthreads();

            gemm_slice(acc1, sm->W1 + rg * W1STR + 128 + kw * 16, W1STR, sm->S4, kw, bg);
            #pragma unroll
            for (int i = 0; i < 4; i++)
                #pragma unroll
                for (int j = 0; j < 4; j++){
                    float2 v = u2f(acc1[i][j]);
                    sm->gpart[(kw * 16 + rg + 4 * i) * SCOL + bg + 8 * j] = v.x + v.y;
                }
            __syncthreads();

            if (tid < 128){
                int dl = tid >> 5, b = tid & 31;
                float gv[4];
                #pragma unroll
                for (int q = 0; q < 4; q++){
                    int r_l = q * 4 + dl;
                    float s = 0.f;
                    #pragma unroll
                    for (int w8 = 0; w8 < 8; w8++)
                        s += sm->gpart[(w8 * 16 + r_l) * SCOL + b];
                    gv[q] = s + sm->bsum[r_l];
                }
                float cn = sigf(gv[1]) * sm->csm1[tid] + sigf(gv[0]) * tanhf(gv[2]);
                sm->csm1[tid] = cn;
                float sn = sigf(gv[3]) * tanhf(cn);
                g_s1[p & 1][b * DDIM + d0 + dl] = sn;
                g_A[((size_t)b * TDIM + (p - 1)) * (2 * DDIM) + d0 + dl] = sn;
            }
        }

        gridbar(gen0 + p + 1);
    }
}

// ------------- parallel attention + direct bf16-split write -------------
__global__ void __launch_bounds__(256) k_attn2(const float* __restrict__ h){
    __shared__ __align__(16) float s1s[8][516];
    __shared__ float sc[8][132];
    const int b = blockIdx.y, t0 = blockIdx.x * 8;
    const int tid = threadIdx.x, w = tid >> 5, lane = tid & 31;
    const size_t arow0 = ((size_t)b * TDIM + t0) * 1024;

    for (int i = tid; i < 1024; i += 256){
        int tt = i >> 7, q = i & 127;
        *(float4*)&s1s[tt][q * 4] = *(const float4*)(g_A + arow0 + (size_t)tt * 1024 + q * 4);
    }
    __syncthreads();

    const float* hb = h + (size_t)b * SDIM * DDIM;

    for (int j = 0; j < 16; j++){
        int s = w * 16 + j;
        const float4* hr = (const float4*)(hb + (size_t)s * DDIM);
        float4 hv[4];
        #pragma unroll
        for (int q = 0; q < 4; q++) hv[q] = hr[lane + 32 * q];
        float p[8];
        #pragma unroll
        for (int tt = 0; tt < 8; tt++){
            float acc = 0.f;
            #pragma unroll
            for (int q = 0; q < 4; q++){
                float4 sv = *(const float4*)&s1s[tt][(lane + 32 * q) * 4];
                acc += hv[q].x * sv.x + hv[q].y * sv.y + hv[q].z * sv.z + hv[q].w * sv.w;
            }
            p[tt] = acc;
        }
        #pragma unroll
        for (int tt = 0; tt < 8; tt++){
            #pragma unroll
            for (int off = 16; off; off >>= 1)
                p[tt] += __shfl_xor_sync(0xffffffffu, p[tt], off);
        }
        #pragma unroll
        for (int tt = 0; tt < 8; tt++)
            if (lane == tt) sc[tt][s] = p[tt];
    }
    __syncthreads();

    {
        float x[4];
        #pragma unroll
        for (int q = 0; q < 4; q++) x[q] = sc[w][lane + 32 * q];
        float mx = fmaxf(fmaxf(x[0], x[1]), fmaxf(x[2], x[3]));
        #pragma unroll
        for (int off = 16; off; off >>= 1) mx = fmaxf(mx, __shfl_xor_sync(0xffffffffu, mx, off));
        float e[4], sum = 0.f;
        #pragma unroll
        for (int q = 0; q < 4; q++){ e[q] = expf(x[q] - mx); sum += e[q]; }
        #pragma unroll
        for (int off = 16; off; off >>= 1) sum += __shfl_xor_sync(0xffffffffu, sum, off);
        float inv = 1.0f / sum;
        #pragma unroll
        for (int q = 0; q < 4; q++) sc[w][lane + 32 * q] = e[q] * inv;
    }
    __syncthreads();

    float az[8][2] = {};
    const int d2 = tid * 2;
    #pragma unroll 4
    for (int s = 0; s < SDIM; s++){
        float2 hv = *(const float2*)(hb + (size_t)s * DDIM + d2);
        #pragma unroll
        for (int tt = 0; tt < 8; tt++){
            float a = sc[tt][s];
            az[tt][0] += a * hv.x;
            az[tt][1] += a * hv.y;
        }
    }
    #pragma unroll
    for (int tt = 0; tt < 8; tt++){
        unsigned hi, lo;
        split2(az[tt][0], az[tt][1], hi, lo);
        size_t off = arow0 + (size_t)tt * 1024 + 512 + d2;
        *(unsigned*)(g_Ah + off) = hi;
        *(unsigned*)(g_Al + off) = lo;
    }
    for (int i = tid; i < 2048; i += 256){
        int tt = i >> 8, q = i & 255;
        float x = s1s[tt][q * 2], y = s1s[tt][q * 2 + 1];
        unsigned hi, lo;
        split2(x, y, hi, lo);
        size_t off = arow0 + (size_t)tt * 1024 + q * 2;
        *(unsigned*)(g_Ah + off) = hi;
        *(unsigned*)(g_Al + off) = lo;
    }
}

// ------------- bf16 hi/lo split of Wout -------------
__global__ void k_cvtW(const float* __restrict__ W){
    const size_t total = (size_t)VSZ * 1024 / 4;
    for (size_t i = (size_t)blockIdx.x * blockDim.x + threadIdx.x; i < total;
         i += (size_t)gridDim.x * blockDim.x){
        float4 v = ((const float4*)W)[i];
        unsigned h0, l0, h1, l1;
        split2(v.x, v.y, h0, l0);
        split2(v.z, v.w, h1, l1);
        ((uint2*)g_Bh)[i] = make_uint2(h0, h1);
        ((uint2*)g_Bl)[i] = make_uint2(l0, l1);
    }
}

// ------------- output GEMM via mma.sync bf16 (3-term split) -------------
#define OST 65536
#define OAH 0
#define OAL 16384
#define OBH 32768
#define OBL 49152

__device__ __forceinline__ uint32_t osw(uint32_t r, uint32_t c8){
    return r * 128u + ((c8 ^ (r & 7u)) * 16u);
}

__global__ void __launch_bounds__(256, 1) k_out_mma(float* __restrict__ out,
                                                    const float* __restrict__ bout){
    extern __shared__ char osm[];
    __shared__ float bias[128];
    const uint32_t sb = smem_u32(osm);
    const int tid = threadIdx.x;
    const int wid = tid >> 5, lane = tid & 31;
    const int wm = wid >> 2, wn = wid & 3;
    const int m0 = blockIdx.x * 128;
    const int n0 = blockIdx.y * 128;

    if (tid < 128) bias[tid] = bout[n0 + tid];

    auto load_chunk = [&](int st, int kc){
        const uint32_t stb = sb + (uint32_t)st * OST;
        #pragma unroll
        for (int q = 0; q < 8; q++){
            int i = tid + q * 256;
            int r = (i & 1023) >> 3, c8 = i & 7;
            const __nv_bfloat16* src = (i < 1024) ? g_Ah : g_Al;
            uint32_t dst = stb + (i < 1024 ? OAH : OAL) + osw((uint32_t)r, (uint32_t)c8);
            CP_ASYNC16(dst, src + (size_t)(m0 + r) * 1024 + kc + c8 * 8);
        }
        #pragma unroll
        for (int q = 0; q < 8; q++){
            int i = tid + q * 256;
            int r = (i & 1023) >> 3, c8 = i & 7;
            const __nv_bfloat16* src = (i < 1024) ? g_Bh : g_Bl;
            uint32_t dst = stb + (i < 1024 ? OBH : OBL) + osw((uint32_t)r, (uint32_t)c8);
            CP_ASYNC16(dst, src + (size_t)(n0 + r) * 1024 + kc + c8 * 8);
        }
        CP_COMMIT();
    };

    float acc[4][4][4] = {};

    load_chunk(0, 0);
    load_chunk(1, 64);
    load_chunk(2, 128);

    #pragma unroll 1
    for (int c = 0; c < 16; c++){
        if      (c < 14) { CP_WAIT(2); }
        else if (c == 14){ CP_WAIT(1); }
        else             { CP_WAIT(0); }
        __syncthreads();

        const uint32_t base = sb + (uint32_t)(c % 3) * OST;
        #pragma unroll
        for (int ks = 0; ks < 4; ks++){
            const int k0 = ks * 16;
            uint32_t Ah[4][4], Al[4][4], Bh[4][2], Bl[4][2];
            {
                uint32_t arow = (uint32_t)(wm * 64 + ((lane >> 3) & 1) * 8 + (lane & 7));
                uint32_t ac8  = (uint32_t)((k0 >> 3) + (lane >> 4));
                #pragma unroll
                for (int f = 0; f < 4; f++){
                    uint32_t off = osw(arow + f * 16, ac8);
                    LDSM4(Ah[f], base + OAH + off);
                    LDSM4(Al[f], base + OAL + off);
                }
            }
            {
                uint32_t brow = (uint32_t)(wn * 32 + (lane & 7));
                uint32_t bc8  = (uint32_t)((k0 >> 3) + ((lane >> 3) & 1));
                #pragma unroll
                for (int g = 0; g < 4; g++){
                    uint32_t off = osw(brow + g * 8, bc8);
                    LDSM2(Bh[g], base + OBH + off);
                    LDSM2(Bl[g], base + OBL + off);
                }
            }
            #pragma unroll
            for (int f = 0; f < 4; f++)
                #pragma unroll
                for (int g = 0; g < 4; g++){
                    MMA_BF16(acc[f][g], Ah[f], Bh[g]);
                    MMA_BF16(acc[f][g], Al[f], Bh[g]);
                    MMA_BF16(acc[f][g], Ah[f], Bl[g]);
                }
        }
        __syncthreads();
        if (c + 3 < 16) load_chunk((c + 3) % 3, (c + 3) * 64);
    }

    const size_t ob = (size_t)blockIdx.x * VSZ * TDIM;
    #pragma unroll
    for (int f = 0; f < 4; f++){
        int m = wm * 64 + f * 16 + (lane >> 2);
        #pragma unroll
        for (int g = 0; g < 4; g++){
            int n = wn * 32 + g * 8 + (lane & 3) * 2;
            float* p = out + ob + (size_t)(n0 + n) * TDIM + m;
            p[0]        = acc[f][g][0] + bias[n];
            p[TDIM]     = acc[f][g][1] + bias[n + 1];
            p[8]        = acc[f][g][2] + bias[n];
            p[8 + TDIM] = acc[f][g][3] + bias[n + 1];
        }
    }
}

// ------------- launcher -------------
extern "C" void kernel_launch(void* const* d_in, const int* in_sizes, int n_in,
                              void* d_out, int out_size){
    const int*   tar  = (const int*)  d_in[0];
    const float* h    = (const float*)d_in[1];
    const float* s0   = (const float*)d_in[2];
    const float* c0   = (const float*)d_in[3];
    const float* emb  = (const float*)d_in[4];
    const float* Wih0 = (const float*)d_in[5];
    const float* Whh0 = (const float*)d_in[6];
    const float* bih0 = (const float*)d_in[7];
    const float* bhh0 = (const float*)d_in[8];
    const float* Wih1 = (const float*)d_in[9];
    const float* Whh1 = (const float*)d_in[10];
    const float* bih1 = (const float*)d_in[11];
    const float* bhh1 = (const float*)d_in[12];
    const float* Wout = (const float*)d_in[13];
    const float* bout = (const float*)d_in[14];
    float* out = (float*)d_out;

    static int attr_set = 0;
    static cudaStream_t s2 = nullptr;
    static cudaEvent_t ev1 = nullptr, ev2 = nullptr;
    if (!attr_set){
        cudaFuncSetAttribute(k_rec, cudaFuncAttributeMaxDynamicSharedMemorySize,
                             (int)sizeof(RecSmem));
        cudaFuncSetAttribute(k_out_mma, cudaFuncAttributeMaxDynamicSharedMemorySize,
                             3 * OST);
        cudaStreamCreateWithFlags(&s2, cudaStreamNonBlocking);
        cudaEventCreateWithFlags(&ev1, cudaEventDisableTiming);
        cudaEventCreateWithFlags(&ev2, cudaEventDisableTiming);
        attr_set = 1;
    }

    // fork: cvtW (independent until k_out_mma) runs concurrently
    cudaEventRecord(ev1, 0);
    cudaStreamWaitEvent(s2, ev1, 0);
    k_cvtW<<<2048, 256, 0, s2>>>(Wout);
    cudaEventRecord(ev2, s2);

    k_init<<<64, 256>>>(s0, c0);
    k_x0<<<dim3(32, 64), 256>>>(tar, emb, Wih0, bih0, bhh0);
    k_rec<<<NCTA, NTHR, sizeof(RecSmem)>>>(c0, Whh0, Wih1, Whh1, bih1, bhh1);
    k_attn2<<<dim3(16, 32), 256>>>(h);

    cudaStreamWaitEvent(0, ev2, 0);
    k_out_mma<<<dim3(32, 250), 256, 3 * OST>>>(out, bout);
}